// round 1
// baseline (speedup 1.0000x reference)
#include <cuda_runtime.h>
#include <math.h>

#define Bsz 4
#define Sq  2048
#define Dm  1024
#define Hn  16
#define HDm 64
#define Mrows (Bsz * Sq)   // 8192

// Scratch (device globals — no allocation in kernel_launch)
__device__ float g_q[(size_t)Mrows * Dm];
__device__ float g_k[(size_t)Mrows * Dm];
__device__ float g_v[(size_t)Mrows * Dm];
__device__ float g_attn[(size_t)Mrows * Dm];

// ---------------------------------------------------------------------------
// SGEMM: Out[M][N] = X[M][K] @ W[N][K]^T   (nn.Linear, no bias)
// 128x128 block, BK=16, 8x8 per-thread micro tile, 256 threads.
// ---------------------------------------------------------------------------
__global__ __launch_bounds__(256) void sgemm_xwT(
    const float* __restrict__ X, const float* __restrict__ W,
    float* __restrict__ Out, int N, int K)
{
    __shared__ float As[16][132];   // k-major, padded
    __shared__ float Bs[16][132];

    const int bm  = blockIdx.y * 128;
    const int bn  = blockIdx.x * 128;
    const int tid = threadIdx.x;
    const int ty  = tid >> 4;       // 0..15
    const int tx  = tid & 15;       // 0..15

    float acc[8][8];
#pragma unroll
    for (int i = 0; i < 8; i++)
#pragma unroll
        for (int j = 0; j < 8; j++) acc[i][j] = 0.f;

    for (int k0 = 0; k0 < K; k0 += 16) {
#pragma unroll
        for (int p = 0; p < 2; p++) {
            int lin = tid + p * 256;         // 0..511
            int row = lin >> 2;              // 0..127
            int c   = lin & 3;               // 0..3 (float4 index along k)
            float4 a = *(const float4*)(X + (size_t)(bm + row) * K + k0 + 4 * c);
            As[4*c+0][row] = a.x; As[4*c+1][row] = a.y;
            As[4*c+2][row] = a.z; As[4*c+3][row] = a.w;
            float4 b = *(const float4*)(W + (size_t)(bn + row) * K + k0 + 4 * c);
            Bs[4*c+0][row] = b.x; Bs[4*c+1][row] = b.y;
            Bs[4*c+2][row] = b.z; Bs[4*c+3][row] = b.w;
        }
        __syncthreads();
#pragma unroll
        for (int kk = 0; kk < 16; kk++) {
            float4 a0 = *(const float4*)&As[kk][ty * 8];
            float4 a1 = *(const float4*)&As[kk][ty * 8 + 4];
            float4 b0 = *(const float4*)&Bs[kk][tx * 8];
            float4 b1 = *(const float4*)&Bs[kk][tx * 8 + 4];
            float av[8] = {a0.x, a0.y, a0.z, a0.w, a1.x, a1.y, a1.z, a1.w};
            float bv[8] = {b0.x, b0.y, b0.z, b0.w, b1.x, b1.y, b1.z, b1.w};
#pragma unroll
            for (int i = 0; i < 8; i++)
#pragma unroll
                for (int j = 0; j < 8; j++)
                    acc[i][j] += av[i] * bv[j];
        }
        __syncthreads();
    }

#pragma unroll
    for (int i = 0; i < 8; i++) {
#pragma unroll
        for (int j = 0; j < 2; j++) {
            float4 v = make_float4(acc[i][4*j], acc[i][4*j+1],
                                   acc[i][4*j+2], acc[i][4*j+3]);
            *(float4*)(Out + (size_t)(bm + ty * 8 + i) * N + bn + tx * 8 + 4 * j) = v;
        }
    }
}

// ---------------------------------------------------------------------------
// Fused flash attention. One block = (b, h, 128-row q tile). 256 threads.
// smem: Qs[64][132] d-major, Ks[64][132] d-major, Vs[128][68] row-major,
//       Ps[128][132] row-major.
// Thread (ty,tx): scores rows ty*8+[0..7], cols tx*8+[0..7];
//                 O      rows ty*8+[0..7], cols tx*4+[0..3].
// ---------------------------------------------------------------------------
#define SM_QS   (64 * 132)
#define SM_KS   (64 * 132)
#define SM_VS   (128 * 68)
#define SM_PS   (128 * 132)
#define ATTN_SMEM_FLOATS (SM_QS + SM_KS + SM_VS + SM_PS)
#define ATTN_SMEM_BYTES  (ATTN_SMEM_FLOATS * 4)   // 169984

__global__ __launch_bounds__(256, 1) void attn_fused(
    const float* __restrict__ Q, const float* __restrict__ Kt,
    const float* __restrict__ Vt, const int* __restrict__ mask,
    float* __restrict__ Out)
{
    extern __shared__ float sm[];
    float* Qs = sm;                       // [64][132]
    float* Ks = Qs + SM_QS;               // [64][132]
    float* Vs = Ks + SM_KS;               // [128][68]
    float* Ps = Vs + SM_VS;               // [128][132]

    const int qb  = blockIdx.x * 128;
    const int h   = blockIdx.y;
    const int b   = blockIdx.z;
    const int tid = threadIdx.x;
    const int ty  = tid >> 4;   // 0..15
    const int tx  = tid & 15;   // 0..15

    const size_t base = ((size_t)b * Sq) * Dm + (size_t)h * HDm;

    // Load Q tile: 128 rows x 64 dims, stored d-major Qs[d][i]
#pragma unroll
    for (int p = 0; p < 8; p++) {
        int lin = tid + 256 * p;          // 0..2047
        int i = lin >> 4;                 // row 0..127
        int c = lin & 15;                 // float4 idx along d
        float4 v = *(const float4*)(Q + base + (size_t)(qb + i) * Dm + 4 * c);
        Qs[(4*c+0)*132 + i] = v.x; Qs[(4*c+1)*132 + i] = v.y;
        Qs[(4*c+2)*132 + i] = v.z; Qs[(4*c+3)*132 + i] = v.w;
    }

    float m_i[8], l_i[8], o[8][4];
#pragma unroll
    for (int r = 0; r < 8; r++) {
        m_i[r] = -INFINITY; l_i[r] = 0.f;
        o[r][0] = o[r][1] = o[r][2] = o[r][3] = 0.f;
    }

    for (int kb = 0; kb < Sq; kb += 128) {
        __syncthreads();   // previous iteration done reading Ks/Vs/Ps
        // Load K tile (d-major) and V tile (row-major)
#pragma unroll
        for (int p = 0; p < 8; p++) {
            int lin = tid + 256 * p;
            int j = lin >> 4;
            int c = lin & 15;
            float4 v = *(const float4*)(Kt + base + (size_t)(kb + j) * Dm + 4 * c);
            Ks[(4*c+0)*132 + j] = v.x; Ks[(4*c+1)*132 + j] = v.y;
            Ks[(4*c+2)*132 + j] = v.z; Ks[(4*c+3)*132 + j] = v.w;
            float4 w = *(const float4*)(Vt + base + (size_t)(kb + j) * Dm + 4 * c);
            *(float4*)&Vs[j * 68 + 4 * c] = w;
        }
        __syncthreads();

        // S = Q @ K^T  (8x8 per thread over d=0..63)
        float sacc[8][8];
#pragma unroll
        for (int r = 0; r < 8; r++)
#pragma unroll
            for (int c = 0; c < 8; c++) sacc[r][c] = 0.f;

#pragma unroll 8
        for (int d = 0; d < 64; d++) {
            float4 a0 = *(const float4*)&Qs[d * 132 + ty * 8];
            float4 a1 = *(const float4*)&Qs[d * 132 + ty * 8 + 4];
            float4 b0 = *(const float4*)&Ks[d * 132 + tx * 8];
            float4 b1 = *(const float4*)&Ks[d * 132 + tx * 8 + 4];
            float av[8] = {a0.x, a0.y, a0.z, a0.w, a1.x, a1.y, a1.z, a1.w};
            float bv[8] = {b0.x, b0.y, b0.z, b0.w, b1.x, b1.y, b1.z, b1.w};
#pragma unroll
            for (int r = 0; r < 8; r++)
#pragma unroll
                for (int c = 0; c < 8; c++)
                    sacc[r][c] += av[r] * bv[c];
        }

        // scale + mask
        const int qrow = qb + ty * 8;
#pragma unroll
        for (int r = 0; r < 8; r++) {
            const int* mrow = mask + (size_t)(qrow + r) * Sq + kb + tx * 8;
#pragma unroll
            for (int c = 0; c < 8; c++) {
                float sv = sacc[r][c] * 0.125f;   // 1/sqrt(64)
                if (mrow[c] == 0) sv = -1e9f;
                sacc[r][c] = sv;
            }
        }

        // online softmax per row (reduce across the 16 tx lanes)
#pragma unroll
        for (int r = 0; r < 8; r++) {
            float mx = sacc[r][0];
#pragma unroll
            for (int c = 1; c < 8; c++) mx = fmaxf(mx, sacc[r][c]);
#pragma unroll
            for (int off = 1; off < 16; off <<= 1)
                mx = fmaxf(mx, __shfl_xor_sync(0xffffffffu, mx, off));
            float mnew  = fmaxf(m_i[r], mx);
            float alpha = __expf(m_i[r] - mnew);
            float rs = 0.f;
#pragma unroll
            for (int c = 0; c < 8; c++) {
                float pv = __expf(sacc[r][c] - mnew);
                sacc[r][c] = pv;
                rs += pv;
            }
#pragma unroll
            for (int off = 1; off < 16; off <<= 1)
                rs += __shfl_xor_sync(0xffffffffu, rs, off);
            l_i[r] = l_i[r] * alpha + rs;
            m_i[r] = mnew;
            o[r][0] *= alpha; o[r][1] *= alpha; o[r][2] *= alpha; o[r][3] *= alpha;
            // stage P
            *(float4*)&Ps[(ty * 8 + r) * 132 + tx * 8] =
                make_float4(sacc[r][0], sacc[r][1], sacc[r][2], sacc[r][3]);
            *(float4*)&Ps[(ty * 8 + r) * 132 + tx * 8 + 4] =
                make_float4(sacc[r][4], sacc[r][5], sacc[r][6], sacc[r][7]);
        }
        __syncthreads();

        // O += P @ V  (rows ty*8+r, cols tx*4+c)
#pragma unroll 4
        for (int kk = 0; kk < 128; kk++) {
            float4 bv = *(const float4*)&Vs[kk * 68 + 4 * tx];
#pragma unroll
            for (int r = 0; r < 8; r++) {
                float a = Ps[(ty * 8 + r) * 132 + kk];
                o[r][0] += a * bv.x; o[r][1] += a * bv.y;
                o[r][2] += a * bv.z; o[r][3] += a * bv.w;
            }
        }
    }

    // epilogue: O / l, write head-interleaved [b, s, h*64+d]
#pragma unroll
    for (int r = 0; r < 8; r++) {
        float inv = 1.f / l_i[r];
        float4 v = make_float4(o[r][0] * inv, o[r][1] * inv,
                               o[r][2] * inv, o[r][3] * inv);
        *(float4*)(Out + base + (size_t)(qb + ty * 8 + r) * Dm + 4 * tx) = v;
    }
}

// ---------------------------------------------------------------------------
extern "C" void kernel_launch(void* const* d_in, const int* in_sizes, int n_in,
                              void* d_out, int out_size)
{
    (void)in_sizes; (void)n_in; (void)out_size;
    const float* query = (const float*)d_in[0];
    const float* key_  = (const float*)d_in[1];
    const float* value = (const float*)d_in[2];
    const int*   mask  = (const int*)d_in[3];
    const float* w_q   = (const float*)d_in[4];
    const float* w_k   = (const float*)d_in[5];
    const float* w_v   = (const float*)d_in[6];
    const float* w_o   = (const float*)d_in[7];
    float* out = (float*)d_out;

    float *q, *k, *v, *attn;
    cudaGetSymbolAddress((void**)&q,    g_q);
    cudaGetSymbolAddress((void**)&k,    g_k);
    cudaGetSymbolAddress((void**)&v,    g_v);
    cudaGetSymbolAddress((void**)&attn, g_attn);

    cudaFuncSetAttribute(attn_fused,
                         cudaFuncAttributeMaxDynamicSharedMemorySize,
                         ATTN_SMEM_BYTES);

    dim3 gg(Dm / 128, Mrows / 128);   // (8, 64)
    sgemm_xwT<<<gg, 256>>>(query, w_q, q, Dm, Dm);
    sgemm_xwT<<<gg, 256>>>(key_,  w_k, k, Dm, Dm);
    sgemm_xwT<<<gg, 256>>>(value, w_v, v, Dm, Dm);

    dim3 ga(Sq / 128, Hn, Bsz);       // (16, 16, 4)
    attn_fused<<<ga, 256, ATTN_SMEM_BYTES>>>(q, k, v, mask, attn);

    sgemm_xwT<<<gg, 256>>>(attn, w_o, out, Dm, Dm);
}

// round 3
// speedup vs baseline: 1.4447x; 1.4447x over previous
#include <cuda_runtime.h>
#include <math.h>
#include <stdint.h>

#define Bsz 4
#define Sq  2048
#define Dm  1024
#define Hn  16
#define HDm 64
#define Mrows (Bsz * Sq)   // 8192

// Scratch (device globals — no allocation in kernel_launch)
__device__ float g_q[(size_t)Mrows * Dm];
__device__ float g_k[(size_t)Mrows * Dm];
__device__ float g_v[(size_t)Mrows * Dm];
__device__ float g_attn[(size_t)Mrows * Dm];

// ===========================================================================
// helpers
// ===========================================================================
static __device__ __forceinline__ uint32_t smem_u32(const void* p) {
    uint32_t a;
    asm("{ .reg .u64 t; cvta.to.shared.u64 t, %1; cvt.u32.u64 %0, t; }"
        : "=r"(a) : "l"(p));
    return a;
}

static __device__ __forceinline__ void cp16(uint32_t dst, const void* src) {
    asm volatile("cp.async.cg.shared.global [%0], [%1], 16;"
                 :: "r"(dst), "l"(src) : "memory");
}
static __device__ __forceinline__ void cp_commit() {
    asm volatile("cp.async.commit_group;" ::: "memory");
}
static __device__ __forceinline__ void cp_wait1() {
    asm volatile("cp.async.wait_group 1;" ::: "memory");
}
static __device__ __forceinline__ void cp_wait0() {
    asm volatile("cp.async.wait_group 0;" ::: "memory");
}

static __device__ __forceinline__ uint32_t f2tf32(float f) {
    uint32_t u;
    asm("cvt.rna.tf32.f32 %0, %1;" : "=r"(u) : "f"(f));
    return u;
}

// D(16x8,f32) += A(16x8,tf32,row) * B(8x8,tf32,col)
static __device__ __forceinline__ void mma_tf32(
    float* d, const uint32_t* a, const uint32_t* b)
{
    asm volatile(
        "mma.sync.aligned.m16n8k8.row.col.f32.tf32.tf32.f32 "
        "{%0,%1,%2,%3}, {%4,%5,%6,%7}, {%8,%9}, {%0,%1,%2,%3};"
        : "+f"(d[0]), "+f"(d[1]), "+f"(d[2]), "+f"(d[3])
        : "r"(a[0]), "r"(a[1]), "r"(a[2]), "r"(a[3]),
          "r"(b[0]), "r"(b[1]));
}

// ===========================================================================
// tf32 tensor-core GEMM: Out[M][N] = X[M][K] @ W[N][K]^T
// CTA 128x128, BK=32, 2-stage cp.async double buffer, 256 threads.
// Warp grid 2(M) x 4(N): each warp 64x32 = 4x4 m16n8k8 tiles.
// smem pitch 36 floats (144B, 16B-aligned, conflict-free frag reads).
// ===========================================================================
#define GM_BK     32
#define GM_PITCH  36
#define GM_STAGE  (128 * GM_PITCH)                  // floats per stage per operand
#define GM_SMEM_FLOATS (4 * GM_STAGE)               // A0 A1 B0 B1
#define GM_SMEM_BYTES  (GM_SMEM_FLOATS * 4)         // 73728

__global__ __launch_bounds__(256) void sgemm_mma(
    const float* __restrict__ X, const float* __restrict__ W,
    float* __restrict__ Out, int N, int K)
{
    extern __shared__ float sm[];
    float* As = sm;                       // [2][128][36]
    float* Bs = sm + 2 * GM_STAGE;        // [2][128][36]
    const uint32_t smb = smem_u32(sm);

    const int tid  = threadIdx.x;
    const int wid  = tid >> 5;
    const int lane = tid & 31;
    const int bm   = blockIdx.y * 128;
    const int bn   = blockIdx.x * 128;

    const int wm = (wid & 1) * 64;        // warp M offset in tile
    const int wn = (wid >> 1) * 32;       // warp N offset in tile

    const int lq = lane >> 2;             // 0..7
    const int lr = lane & 3;              // 0..3

    float d[4][4][4];
#pragma unroll
    for (int mt = 0; mt < 4; mt++)
#pragma unroll
        for (int nt = 0; nt < 4; nt++)
#pragma unroll
            for (int i = 0; i < 4; i++) d[mt][nt][i] = 0.f;

    const int nchunks = K / GM_BK;        // 32

    // stage loader: chunk -> stage (chunk&1)
    auto load_stage = [&](int chunk) {
        const int s = chunk & 1;
        const int k0 = chunk * GM_BK;
#pragma unroll
        for (int p = 0; p < 4; p++) {
            int idx = tid + 256 * p;      // 0..1023
            int row = idx >> 3;           // 0..127
            int c4  = (idx & 7) * 4;      // float offset in BK
            uint32_t da = smb + (uint32_t)(s * GM_STAGE + row * GM_PITCH + c4) * 4;
            cp16(da, X + (size_t)(bm + row) * K + k0 + c4);
            uint32_t db = smb + (uint32_t)((2 * GM_STAGE) + s * GM_STAGE + row * GM_PITCH + c4) * 4;
            cp16(db, W + (size_t)(bn + row) * K + k0 + c4);
        }
        cp_commit();
    };

    load_stage(0);
    load_stage(1);

    for (int j = 0; j < nchunks; j++) {
        if (j + 1 < nchunks) cp_wait1(); else cp_wait0();
        __syncthreads();

        const int s = j & 1;
        const float* as = As + s * GM_STAGE;
        const float* bs = Bs + s * GM_STAGE;

#pragma unroll
        for (int kk = 0; kk < GM_BK; kk += 8) {
            uint32_t af[4][4], bf[4][2];
#pragma unroll
            for (int mt = 0; mt < 4; mt++) {
                const float* ap = as + (wm + mt * 16 + lq) * GM_PITCH + kk + lr;
                af[mt][0] = f2tf32(ap[0]);
                af[mt][1] = f2tf32(ap[8 * GM_PITCH]);
                af[mt][2] = f2tf32(ap[4]);
                af[mt][3] = f2tf32(ap[8 * GM_PITCH + 4]);
            }
#pragma unroll
            for (int nt = 0; nt < 4; nt++) {
                const float* bp = bs + (wn + nt * 8 + lq) * GM_PITCH + kk + lr;
                bf[nt][0] = f2tf32(bp[0]);
                bf[nt][1] = f2tf32(bp[4]);
            }
#pragma unroll
            for (int mt = 0; mt < 4; mt++)
#pragma unroll
                for (int nt = 0; nt < 4; nt++)
                    mma_tf32(d[mt][nt], af[mt], bf[nt]);
        }
        __syncthreads();
        if (j + 2 < nchunks) load_stage(j + 2);
    }

    // epilogue: direct float2 stores
#pragma unroll
    for (int mt = 0; mt < 4; mt++) {
#pragma unroll
        for (int nt = 0; nt < 4; nt++) {
            int r = bm + wm + mt * 16 + lq;
            int c = bn + wn + nt * 8 + 2 * lr;
            *(float2*)(Out + (size_t)r * N + c) =
                make_float2(d[mt][nt][0], d[mt][nt][1]);
            *(float2*)(Out + (size_t)(r + 8) * N + c) =
                make_float2(d[mt][nt][2], d[mt][nt][3]);
        }
    }
}

// ===========================================================================
// Fused flash attention (fp32 SIMT — unchanged)
// ===========================================================================
#define SM_QS   (64 * 132)
#define SM_KS   (64 * 132)
#define SM_VS   (128 * 68)
#define SM_PS   (128 * 132)
#define ATTN_SMEM_FLOATS (SM_QS + SM_KS + SM_VS + SM_PS)
#define ATTN_SMEM_BYTES  (ATTN_SMEM_FLOATS * 4)

__global__ __launch_bounds__(256, 1) void attn_fused(
    const float* __restrict__ Q, const float* __restrict__ Kt,
    const float* __restrict__ Vt, const int* __restrict__ mask,
    float* __restrict__ Out)
{
    extern __shared__ float smf[];
    float* Qs = smf;
    float* Ks = Qs + SM_QS;
    float* Vs = Ks + SM_KS;
    float* Ps = Vs + SM_VS;

    const int qb  = blockIdx.x * 128;
    const int h   = blockIdx.y;
    const int b   = blockIdx.z;
    const int tid = threadIdx.x;
    const int ty  = tid >> 4;
    const int tx  = tid & 15;

    const size_t base = ((size_t)b * Sq) * Dm + (size_t)h * HDm;

#pragma unroll
    for (int p = 0; p < 8; p++) {
        int lin = tid + 256 * p;
        int i = lin >> 4;
        int c = lin & 15;
        float4 v = *(const float4*)(Q + base + (size_t)(qb + i) * Dm + 4 * c);
        Qs[(4*c+0)*132 + i] = v.x; Qs[(4*c+1)*132 + i] = v.y;
        Qs[(4*c+2)*132 + i] = v.z; Qs[(4*c+3)*132 + i] = v.w;
    }

    float m_i[8], l_i[8], o[8][4];
#pragma unroll
    for (int r = 0; r < 8; r++) {
        m_i[r] = -INFINITY; l_i[r] = 0.f;
        o[r][0] = o[r][1] = o[r][2] = o[r][3] = 0.f;
    }

    for (int kb = 0; kb < Sq; kb += 128) {
        __syncthreads();
#pragma unroll
        for (int p = 0; p < 8; p++) {
            int lin = tid + 256 * p;
            int j = lin >> 4;
            int c = lin & 15;
            float4 v = *(const float4*)(Kt + base + (size_t)(kb + j) * Dm + 4 * c);
            Ks[(4*c+0)*132 + j] = v.x; Ks[(4*c+1)*132 + j] = v.y;
            Ks[(4*c+2)*132 + j] = v.z; Ks[(4*c+3)*132 + j] = v.w;
            float4 w = *(const float4*)(Vt + base + (size_t)(kb + j) * Dm + 4 * c);
            *(float4*)&Vs[j * 68 + 4 * c] = w;
        }
        __syncthreads();

        float sacc[8][8];
#pragma unroll
        for (int r = 0; r < 8; r++)
#pragma unroll
            for (int c = 0; c < 8; c++) sacc[r][c] = 0.f;

#pragma unroll 8
        for (int dd = 0; dd < 64; dd++) {
            float4 a0 = *(const float4*)&Qs[dd * 132 + ty * 8];
            float4 a1 = *(const float4*)&Qs[dd * 132 + ty * 8 + 4];
            float4 b0 = *(const float4*)&Ks[dd * 132 + tx * 8];
            float4 b1 = *(const float4*)&Ks[dd * 132 + tx * 8 + 4];
            float av[8] = {a0.x, a0.y, a0.z, a0.w, a1.x, a1.y, a1.z, a1.w};
            float bv[8] = {b0.x, b0.y, b0.z, b0.w, b1.x, b1.y, b1.z, b1.w};
#pragma unroll
            for (int r = 0; r < 8; r++)
#pragma unroll
                for (int c = 0; c < 8; c++)
                    sacc[r][c] += av[r] * bv[c];
        }

        const int qrow = qb + ty * 8;
#pragma unroll
        for (int r = 0; r < 8; r++) {
            const int* mrow = mask + (size_t)(qrow + r) * Sq + kb + tx * 8;
#pragma unroll
            for (int c = 0; c < 8; c++) {
                float sv = sacc[r][c] * 0.125f;
                if (mrow[c] == 0) sv = -1e9f;
                sacc[r][c] = sv;
            }
        }

#pragma unroll
        for (int r = 0; r < 8; r++) {
            float mx = sacc[r][0];
#pragma unroll
            for (int c = 1; c < 8; c++) mx = fmaxf(mx, sacc[r][c]);
#pragma unroll
            for (int off = 1; off < 16; off <<= 1)
                mx = fmaxf(mx, __shfl_xor_sync(0xffffffffu, mx, off));
            float mnew  = fmaxf(m_i[r], mx);
            float alpha = __expf(m_i[r] - mnew);
            float rs = 0.f;
#pragma unroll
            for (int c = 0; c < 8; c++) {
                float pv = __expf(sacc[r][c] - mnew);
                sacc[r][c] = pv;
                rs += pv;
            }
#pragma unroll
            for (int off = 1; off < 16; off <<= 1)
                rs += __shfl_xor_sync(0xffffffffu, rs, off);
            l_i[r] = l_i[r] * alpha + rs;
            m_i[r] = mnew;
            o[r][0] *= alpha; o[r][1] *= alpha; o[r][2] *= alpha; o[r][3] *= alpha;
            *(float4*)&Ps[(ty * 8 + r) * 132 + tx * 8] =
                make_float4(sacc[r][0], sacc[r][1], sacc[r][2], sacc[r][3]);
            *(float4*)&Ps[(ty * 8 + r) * 132 + tx * 8 + 4] =
                make_float4(sacc[r][4], sacc[r][5], sacc[r][6], sacc[r][7]);
        }
        __syncthreads();

#pragma unroll 4
        for (int kk = 0; kk < 128; kk++) {
            float4 bv = *(const float4*)&Vs[kk * 68 + 4 * tx];
#pragma unroll
            for (int r = 0; r < 8; r++) {
                float a = Ps[(ty * 8 + r) * 132 + kk];
                o[r][0] += a * bv.x; o[r][1] += a * bv.y;
                o[r][2] += a * bv.z; o[r][3] += a * bv.w;
            }
        }
    }

#pragma unroll
    for (int r = 0; r < 8; r++) {
        float inv = 1.f / l_i[r];
        float4 v = make_float4(o[r][0] * inv, o[r][1] * inv,
                               o[r][2] * inv, o[r][3] * inv);
        *(float4*)(Out + base + (size_t)(qb + ty * 8 + r) * Dm + 4 * tx) = v;
    }
}

// ===========================================================================
extern "C" void kernel_launch(void* const* d_in, const int* in_sizes, int n_in,
                              void* d_out, int out_size)
{
    (void)in_sizes; (void)n_in; (void)out_size;
    const float* query = (const float*)d_in[0];
    const float* key_  = (const float*)d_in[1];
    const float* value = (const float*)d_in[2];
    const int*   mask  = (const int*)d_in[3];
    const float* w_q   = (const float*)d_in[4];
    const float* w_k   = (const float*)d_in[5];
    const float* w_v   = (const float*)d_in[6];
    const float* w_o   = (const float*)d_in[7];
    float* out = (float*)d_out;

    float *q, *k, *v, *attn;
    cudaGetSymbolAddress((void**)&q,    g_q);
    cudaGetSymbolAddress((void**)&k,    g_k);
    cudaGetSymbolAddress((void**)&v,    g_v);
    cudaGetSymbolAddress((void**)&attn, g_attn);

    cudaFuncSetAttribute(sgemm_mma,
                         cudaFuncAttributeMaxDynamicSharedMemorySize,
                         GM_SMEM_BYTES);
    cudaFuncSetAttribute(attn_fused,
                         cudaFuncAttributeMaxDynamicSharedMemorySize,
                         ATTN_SMEM_BYTES);

    dim3 gg(Dm / 128, Mrows / 128);   // (8, 64)
    sgemm_mma<<<gg, 256, GM_SMEM_BYTES>>>(query, w_q, q, Dm, Dm);
    sgemm_mma<<<gg, 256, GM_SMEM_BYTES>>>(key_,  w_k, k, Dm, Dm);
    sgemm_mma<<<gg, 256, GM_SMEM_BYTES>>>(value, w_v, v, Dm, Dm);

    dim3 ga(Sq / 128, Hn, Bsz);       // (16, 16, 4)
    attn_fused<<<ga, 256, ATTN_SMEM_BYTES>>>(q, k, v, mask, attn);

    sgemm_mma<<<gg, 256, GM_SMEM_BYTES>>>(attn, w_o, out, Dm, Dm);
}

// round 4
// speedup vs baseline: 2.9942x; 2.0725x over previous
#include <cuda_runtime.h>
#include <math.h>
#include <stdint.h>

#define Bsz 4
#define Sq  2048
#define Dm  1024
#define Hn  16
#define HDm 64
#define Mrows (Bsz * Sq)   // 8192

// Scratch (device globals — no allocation in kernel_launch)
__device__ float g_q[(size_t)Mrows * Dm];
__device__ float g_k[(size_t)Mrows * Dm];
__device__ float g_v[(size_t)Mrows * Dm];
__device__ float g_attn[(size_t)Mrows * Dm];
__device__ int   g_maskflag[256];     // [qtile][ktile] has-any-zero

// ===========================================================================
// helpers
// ===========================================================================
static __device__ __forceinline__ uint32_t smem_u32(const void* p) {
    uint32_t a;
    asm("{ .reg .u64 t; cvta.to.shared.u64 t, %1; cvt.u32.u64 %0, t; }"
        : "=r"(a) : "l"(p));
    return a;
}

static __device__ __forceinline__ void cp16(uint32_t dst, const void* src) {
    asm volatile("cp.async.cg.shared.global [%0], [%1], 16;"
                 :: "r"(dst), "l"(src) : "memory");
}
static __device__ __forceinline__ void cp_commit() {
    asm volatile("cp.async.commit_group;" ::: "memory");
}
static __device__ __forceinline__ void cp_wait1() {
    asm volatile("cp.async.wait_group 1;" ::: "memory");
}
static __device__ __forceinline__ void cp_wait0() {
    asm volatile("cp.async.wait_group 0;" ::: "memory");
}

static __device__ __forceinline__ uint32_t f2tf32(float f) {
    uint32_t u;
    asm("cvt.rna.tf32.f32 %0, %1;" : "=r"(u) : "f"(f));
    return u;
}

// D(16x8,f32) += A(16x8,tf32,row) * B(8x8,tf32,col)
static __device__ __forceinline__ void mma_tf32(
    float* d, const uint32_t* a, const uint32_t* b)
{
    asm volatile(
        "mma.sync.aligned.m16n8k8.row.col.f32.tf32.tf32.f32 "
        "{%0,%1,%2,%3}, {%4,%5,%6,%7}, {%8,%9}, {%0,%1,%2,%3};"
        : "+f"(d[0]), "+f"(d[1]), "+f"(d[2]), "+f"(d[3])
        : "r"(a[0]), "r"(a[1]), "r"(a[2]), "r"(a[3]),
          "r"(b[0]), "r"(b[1]));
}

// ===========================================================================
// tf32 tensor-core GEMM: Out[M][N] = X[M][K] @ W[N][K]^T   (unchanged R2)
// ===========================================================================
#define GM_BK     32
#define GM_PITCH  36
#define GM_STAGE  (128 * GM_PITCH)
#define GM_SMEM_FLOATS (4 * GM_STAGE)
#define GM_SMEM_BYTES  (GM_SMEM_FLOATS * 4)

__global__ __launch_bounds__(256) void sgemm_mma(
    const float* __restrict__ X, const float* __restrict__ W,
    float* __restrict__ Out, int N, int K)
{
    extern __shared__ float sm[];
    float* As = sm;
    float* Bs = sm + 2 * GM_STAGE;
    const uint32_t smb = smem_u32(sm);

    const int tid  = threadIdx.x;
    const int wid  = tid >> 5;
    const int lane = tid & 31;
    const int bm   = blockIdx.y * 128;
    const int bn   = blockIdx.x * 128;

    const int wm = (wid & 1) * 64;
    const int wn = (wid >> 1) * 32;

    const int lq = lane >> 2;
    const int lr = lane & 3;

    float d[4][4][4];
#pragma unroll
    for (int mt = 0; mt < 4; mt++)
#pragma unroll
        for (int nt = 0; nt < 4; nt++)
#pragma unroll
            for (int i = 0; i < 4; i++) d[mt][nt][i] = 0.f;

    const int nchunks = K / GM_BK;

    auto load_stage = [&](int chunk) {
        const int s = chunk & 1;
        const int k0 = chunk * GM_BK;
#pragma unroll
        for (int p = 0; p < 4; p++) {
            int idx = tid + 256 * p;
            int row = idx >> 3;
            int c4  = (idx & 7) * 4;
            uint32_t da = smb + (uint32_t)(s * GM_STAGE + row * GM_PITCH + c4) * 4;
            cp16(da, X + (size_t)(bm + row) * K + k0 + c4);
            uint32_t db = smb + (uint32_t)((2 * GM_STAGE) + s * GM_STAGE + row * GM_PITCH + c4) * 4;
            cp16(db, W + (size_t)(bn + row) * K + k0 + c4);
        }
        cp_commit();
    };

    load_stage(0);
    load_stage(1);

    for (int j = 0; j < nchunks; j++) {
        if (j + 1 < nchunks) cp_wait1(); else cp_wait0();
        __syncthreads();

        const int s = j & 1;
        const float* as = As + s * GM_STAGE;
        const float* bs = Bs + s * GM_STAGE;

#pragma unroll
        for (int kk = 0; kk < GM_BK; kk += 8) {
            uint32_t af[4][4], bf[4][2];
#pragma unroll
            for (int mt = 0; mt < 4; mt++) {
                const float* ap = as + (wm + mt * 16 + lq) * GM_PITCH + kk + lr;
                af[mt][0] = f2tf32(ap[0]);
                af[mt][1] = f2tf32(ap[8 * GM_PITCH]);
                af[mt][2] = f2tf32(ap[4]);
                af[mt][3] = f2tf32(ap[8 * GM_PITCH + 4]);
            }
#pragma unroll
            for (int nt = 0; nt < 4; nt++) {
                const float* bp = bs + (wn + nt * 8 + lq) * GM_PITCH + kk + lr;
                bf[nt][0] = f2tf32(bp[0]);
                bf[nt][1] = f2tf32(bp[4]);
            }
#pragma unroll
            for (int mt = 0; mt < 4; mt++)
#pragma unroll
                for (int nt = 0; nt < 4; nt++)
                    mma_tf32(d[mt][nt], af[mt], bf[nt]);
        }
        __syncthreads();
        if (j + 2 < nchunks) load_stage(j + 2);
    }

#pragma unroll
    for (int mt = 0; mt < 4; mt++) {
#pragma unroll
        for (int nt = 0; nt < 4; nt++) {
            int r = bm + wm + mt * 16 + lq;
            int c = bn + wn + nt * 8 + 2 * lr;
            *(float2*)(Out + (size_t)r * N + c) =
                make_float2(d[mt][nt][0], d[mt][nt][1]);
            *(float2*)(Out + (size_t)(r + 8) * N + c) =
                make_float2(d[mt][nt][2], d[mt][nt][3]);
        }
    }
}

// ===========================================================================
// mask tile flags: flag[qt*16+kt] = 1 if any zero in that 128x128 mask tile
// ===========================================================================
__global__ __launch_bounds__(256) void mask_flags(const int* __restrict__ mask)
{
    const int kt = blockIdx.x & 15;
    const int qt = blockIdx.x >> 4;
    const int tid = threadIdx.x;
    int any0 = 0;
#pragma unroll
    for (int p = 0; p < 16; p++) {
        int lin = (tid + 256 * p) * 4;       // 0..65532, int4 granule
        int row = lin >> 7;                  // 0..127
        int col = lin & 127;
        int4 m = *(const int4*)(mask + (size_t)(qt * 128 + row) * Sq + kt * 128 + col);
        any0 |= (m.x == 0) | (m.y == 0) | (m.z == 0) | (m.w == 0);
    }
    any0 = __syncthreads_or(any0);
    if (tid == 0) g_maskflag[blockIdx.x] = any0;
}

// ===========================================================================
// Tensor-core flash attention (tf32 mma).
// One CTA = (qtile 128, h, b), 256 threads = 8 warps; warp w owns Q rows
// [16w, 16w+16). K/V double-buffered via cp.async. P staged via per-warp smem.
// ===========================================================================
#define KP 68                                 // K smem pitch (floats)
#define VP 72                                 // V smem pitch
#define PP 132                                // P smem pitch
#define KSTG (128 * KP)
#define VSTG (128 * VP)
#define PWARP (16 * PP)
#define ATT_K_OFF   0
#define ATT_V_OFF   (2 * KSTG)
#define ATT_P_OFF   (2 * KSTG + 2 * VSTG)
#define ATT_SMEM_FLOATS (2 * KSTG + 2 * VSTG + 8 * PWARP)
#define ATT_SMEM_BYTES  (ATT_SMEM_FLOATS * 4)   // 210944

__global__ __launch_bounds__(256, 1) void attn_mma(
    const float* __restrict__ Q, const float* __restrict__ Kg,
    const float* __restrict__ Vg, const int* __restrict__ mask,
    float* __restrict__ Out)
{
    extern __shared__ float sm[];
    float* Ks = sm + ATT_K_OFF;
    float* Vs = sm + ATT_V_OFF;
    float* Pw = sm + ATT_P_OFF;               // warp regions
    const uint32_t smb = smem_u32(sm);

    const int qt  = blockIdx.x;
    const int qb  = qt * 128;
    const int h   = blockIdx.y;
    const int b   = blockIdx.z;
    const int tid = threadIdx.x;
    const int w   = tid >> 5;
    const int lane = tid & 31;
    const int lq  = lane >> 2;                 // 0..7
    const int lr  = lane & 3;                  // 0..3

    const size_t base = ((size_t)b * Sq) * Dm + (size_t)h * HDm;
    float* Pme = Pw + w * PWARP;

    // ---- load K/V tile kb -> buffer s
    auto load_kv = [&](int kb, int s) {
#pragma unroll
        for (int p = 0; p < 8; p++) {
            int idx = tid + 256 * p;           // 0..2047
            int row = idx >> 4;                // 0..127
            int c4  = (idx & 15) * 4;          // 0..60
            const float* kp = Kg + base + (size_t)(kb + row) * Dm + c4;
            const float* vp = Vg + base + (size_t)(kb + row) * Dm + c4;
            cp16(smb + (uint32_t)(ATT_V_OFF + s * VSTG + row * VP + c4) * 4, vp);
            cp16(smb + (uint32_t)(ATT_K_OFF + s * KSTG + row * KP + c4) * 4, kp);
        }
        cp_commit();
    };

    // ---- prologue: stage Q (into P area, pitch KP) + K/V tile 0
    {
#pragma unroll
        for (int p = 0; p < 8; p++) {
            int idx = tid + 256 * p;
            int row = idx >> 4;
            int c4  = (idx & 15) * 4;
            cp16(smb + (uint32_t)(ATT_P_OFF + row * KP + c4) * 4,
                 Q + base + (size_t)(qb + row) * Dm + c4);
        }
        cp_commit();
        load_kv(0, 0);
        cp_wait0();
        __syncthreads();
    }

    // ---- Q fragments (scale folded), rows w*16+lq / +8
    uint32_t qf[8][4];
    {
        const float* qs = Pw + (w * 16 + lq) * KP;        // row lq
        const float* qs8 = qs + 8 * KP;                    // row lq+8
#pragma unroll
        for (int kt = 0; kt < 8; kt++) {
            qf[kt][0] = f2tf32(0.125f * qs [kt * 8 + lr]);
            qf[kt][1] = f2tf32(0.125f * qs8[kt * 8 + lr]);
            qf[kt][2] = f2tf32(0.125f * qs [kt * 8 + lr + 4]);
            qf[kt][3] = f2tf32(0.125f * qs8[kt * 8 + lr + 4]);
        }
    }

    float o[8][4];
#pragma unroll
    for (int nt = 0; nt < 8; nt++)
        o[nt][0] = o[nt][1] = o[nt][2] = o[nt][3] = 0.f;
    float m0 = -INFINITY, m1 = -INFINITY, l0 = 0.f, l1 = 0.f;

    const int qrow0 = qb + w * 16 + lq;

    for (int kt_i = 0; kt_i < 16; kt_i++) {
        const int kb = kt_i * 128;
        const int s  = kt_i & 1;
        cp_wait0();
        __syncthreads();
        if (kt_i + 1 < 16) load_kv(kb + 128, s ^ 1);

        const float* ks = Ks + s * KSTG;
        const float* vs = Vs + s * VSTG;

        // ---- S = Q @ K^T : d[nt][4], nt over 16 n-tiles (128 keys)
        float d[16][4];
#pragma unroll
        for (int nt = 0; nt < 16; nt++)
            d[nt][0] = d[nt][1] = d[nt][2] = d[nt][3] = 0.f;

#pragma unroll
        for (int kt = 0; kt < 8; kt++) {
            uint32_t bf[16][2];
#pragma unroll
            for (int nt = 0; nt < 16; nt++) {
                const float* bp = ks + (nt * 8 + lq) * KP + kt * 8 + lr;
                bf[nt][0] = f2tf32(bp[0]);
                bf[nt][1] = f2tf32(bp[4]);
            }
#pragma unroll
            for (int nt = 0; nt < 16; nt++)
                mma_tf32(d[nt], qf[kt], bf[nt]);
        }

        // ---- mask (slow path only when tile has zeros)
        if (g_maskflag[qt * 16 + kt_i]) {
            const int* mr0 = mask + (size_t)qrow0 * Sq + kb + 2 * lr;
            const int* mr1 = mr0 + 8 * Sq;
#pragma unroll
            for (int nt = 0; nt < 16; nt++) {
                int2 a = *(const int2*)(mr0 + nt * 8);
                int2 c = *(const int2*)(mr1 + nt * 8);
                if (a.x == 0) d[nt][0] = -1e9f;
                if (a.y == 0) d[nt][1] = -1e9f;
                if (c.x == 0) d[nt][2] = -1e9f;
                if (c.y == 0) d[nt][3] = -1e9f;
            }
        }

        // ---- online softmax (rows lq and lq+8), reduce across quad (lr)
        float mx0 = -INFINITY, mx1 = -INFINITY;
#pragma unroll
        for (int nt = 0; nt < 16; nt++) {
            mx0 = fmaxf(mx0, fmaxf(d[nt][0], d[nt][1]));
            mx1 = fmaxf(mx1, fmaxf(d[nt][2], d[nt][3]));
        }
        mx0 = fmaxf(mx0, __shfl_xor_sync(0xffffffffu, mx0, 1));
        mx0 = fmaxf(mx0, __shfl_xor_sync(0xffffffffu, mx0, 2));
        mx1 = fmaxf(mx1, __shfl_xor_sync(0xffffffffu, mx1, 1));
        mx1 = fmaxf(mx1, __shfl_xor_sync(0xffffffffu, mx1, 2));

        float mn0 = fmaxf(m0, mx0), mn1 = fmaxf(m1, mx1);
        float al0 = __expf(m0 - mn0), al1 = __expf(m1 - mn1);
        m0 = mn0; m1 = mn1;

        float rs0 = 0.f, rs1 = 0.f;
#pragma unroll
        for (int nt = 0; nt < 16; nt++) {
            float p0 = __expf(d[nt][0] - mn0);
            float p1 = __expf(d[nt][1] - mn0);
            float p2 = __expf(d[nt][2] - mn1);
            float p3 = __expf(d[nt][3] - mn1);
            rs0 += p0 + p1; rs1 += p2 + p3;
            *(float2*)&Pme[lq * PP + nt * 8 + 2 * lr]       = make_float2(p0, p1);
            *(float2*)&Pme[(lq + 8) * PP + nt * 8 + 2 * lr] = make_float2(p2, p3);
        }
        rs0 += __shfl_xor_sync(0xffffffffu, rs0, 1);
        rs0 += __shfl_xor_sync(0xffffffffu, rs0, 2);
        rs1 += __shfl_xor_sync(0xffffffffu, rs1, 1);
        rs1 += __shfl_xor_sync(0xffffffffu, rs1, 2);
        l0 = l0 * al0 + rs0;
        l1 = l1 * al1 + rs1;

#pragma unroll
        for (int nt = 0; nt < 8; nt++) {
            o[nt][0] *= al0; o[nt][1] *= al0;
            o[nt][2] *= al1; o[nt][3] *= al1;
        }
        __syncwarp();

        // ---- O += P @ V  (K dim = 128 keys, 16 k-steps; N = 64 dims)
#pragma unroll
        for (int kt = 0; kt < 16; kt++) {
            uint32_t af[4];
            af[0] = f2tf32(Pme[lq * PP + kt * 8 + lr]);
            af[1] = f2tf32(Pme[(lq + 8) * PP + kt * 8 + lr]);
            af[2] = f2tf32(Pme[lq * PP + kt * 8 + lr + 4]);
            af[3] = f2tf32(Pme[(lq + 8) * PP + kt * 8 + lr + 4]);
            const float* v0 = vs + (kt * 8 + lr) * VP + lq;
            const float* v4 = v0 + 4 * VP;
#pragma unroll
            for (int nt = 0; nt < 8; nt++) {
                uint32_t bf[2];
                bf[0] = f2tf32(v0[nt * 8]);
                bf[1] = f2tf32(v4[nt * 8]);
                mma_tf32(o[nt], af, bf);
            }
        }
        __syncwarp();
    }

    // ---- epilogue
    float inv0 = 1.f / l0, inv1 = 1.f / l1;
    float* out0 = Out + base + (size_t)qrow0 * Dm;
    float* out1 = out0 + (size_t)8 * Dm;
#pragma unroll
    for (int nt = 0; nt < 8; nt++) {
        *(float2*)(out0 + nt * 8 + 2 * lr) = make_float2(o[nt][0] * inv0, o[nt][1] * inv0);
        *(float2*)(out1 + nt * 8 + 2 * lr) = make_float2(o[nt][2] * inv1, o[nt][3] * inv1);
    }
}

// ===========================================================================
extern "C" void kernel_launch(void* const* d_in, const int* in_sizes, int n_in,
                              void* d_out, int out_size)
{
    (void)in_sizes; (void)n_in; (void)out_size;
    const float* query = (const float*)d_in[0];
    const float* key_  = (const float*)d_in[1];
    const float* value = (const float*)d_in[2];
    const int*   mask  = (const int*)d_in[3];
    const float* w_q   = (const float*)d_in[4];
    const float* w_k   = (const float*)d_in[5];
    const float* w_v   = (const float*)d_in[6];
    const float* w_o   = (const float*)d_in[7];
    float* out = (float*)d_out;

    float *q, *k, *v, *attn;
    cudaGetSymbolAddress((void**)&q,    g_q);
    cudaGetSymbolAddress((void**)&k,    g_k);
    cudaGetSymbolAddress((void**)&v,    g_v);
    cudaGetSymbolAddress((void**)&attn, g_attn);

    cudaFuncSetAttribute(sgemm_mma,
                         cudaFuncAttributeMaxDynamicSharedMemorySize,
                         GM_SMEM_BYTES);
    cudaFuncSetAttribute(attn_mma,
                         cudaFuncAttributeMaxDynamicSharedMemorySize,
                         ATT_SMEM_BYTES);

    mask_flags<<<256, 256>>>(mask);

    dim3 gg(Dm / 128, Mrows / 128);   // (8, 64)
    sgemm_mma<<<gg, 256, GM_SMEM_BYTES>>>(query, w_q, q, Dm, Dm);
    sgemm_mma<<<gg, 256, GM_SMEM_BYTES>>>(key_,  w_k, k, Dm, Dm);
    sgemm_mma<<<gg, 256, GM_SMEM_BYTES>>>(value, w_v, v, Dm, Dm);

    dim3 ga(Sq / 128, Hn, Bsz);       // (16, 16, 4)
    attn_mma<<<ga, 256, ATT_SMEM_BYTES>>>(q, k, v, mask, attn);

    sgemm_mma<<<gg, 256, GM_SMEM_BYTES>>>(attn, w_o, out, Dm, Dm);
}

// round 5
// speedup vs baseline: 3.4704x; 1.1590x over previous
#include <cuda_runtime.h>
#include <math.h>
#include <stdint.h>

#define Bsz 4
#define Sq  2048
#define Dm  1024
#define Hn  16
#define HDm 64
#define Mrows (Bsz * Sq)   // 8192

// Scratch (device globals — no allocation in kernel_launch)
__device__ float g_q[(size_t)Mrows * Dm];
__device__ float g_k[(size_t)Mrows * Dm];
__device__ float g_v[(size_t)Mrows * Dm];
__device__ float g_attn[(size_t)Mrows * Dm];
__device__ float g_xq[(size_t)Mrows * Dm];     // pre-rounded query
__device__ float g_xk[(size_t)Mrows * Dm];     // pre-rounded key
__device__ float g_xv[(size_t)Mrows * Dm];     // pre-rounded value
__device__ float g_wq[(size_t)Dm * Dm];
__device__ float g_wk[(size_t)Dm * Dm];
__device__ float g_wv[(size_t)Dm * Dm];
__device__ float g_wo[(size_t)Dm * Dm];
__device__ int   g_maskflag[256];

// ===========================================================================
// helpers
// ===========================================================================
static __device__ __forceinline__ uint32_t smem_u32(const void* p) {
    uint32_t a;
    asm("{ .reg .u64 t; cvta.to.shared.u64 t, %1; cvt.u32.u64 %0, t; }"
        : "=r"(a) : "l"(p));
    return a;
}

static __device__ __forceinline__ void cp16(uint32_t dst, const void* src) {
    asm volatile("cp.async.cg.shared.global [%0], [%1], 16;"
                 :: "r"(dst), "l"(src) : "memory");
}
static __device__ __forceinline__ void cp_commit() {
    asm volatile("cp.async.commit_group;" ::: "memory");
}
static __device__ __forceinline__ void cp_wait1() {
    asm volatile("cp.async.wait_group 1;" ::: "memory");
}
static __device__ __forceinline__ void cp_wait0() {
    asm volatile("cp.async.wait_group 0;" ::: "memory");
}

static __device__ __forceinline__ uint32_t f2tf32(float f) {
    uint32_t u;
    asm("cvt.rna.tf32.f32 %0, %1;" : "=r"(u) : "f"(f));
    return u;
}
static __device__ __forceinline__ float tf32r(float f) {
    return __uint_as_float(f2tf32(f));
}

// D(16x8,f32) += A(16x8,tf32,row) * B(8x8,tf32,col)
static __device__ __forceinline__ void mma_tf32(
    float* d, const uint32_t* a, const uint32_t* b)
{
    asm volatile(
        "mma.sync.aligned.m16n8k8.row.col.f32.tf32.tf32.f32 "
        "{%0,%1,%2,%3}, {%4,%5,%6,%7}, {%8,%9}, {%0,%1,%2,%3};"
        : "+f"(d[0]), "+f"(d[1]), "+f"(d[2]), "+f"(d[3])
        : "r"(a[0]), "r"(a[1]), "r"(a[2]), "r"(a[3]),
          "r"(b[0]), "r"(b[1]));
}

// ===========================================================================
// elementwise tf32 pre-round
// ===========================================================================
__global__ __launch_bounds__(256) void tf32_round_k(
    const float* __restrict__ src, float* __restrict__ dst, int n4)
{
    int i = blockIdx.x * 256 + threadIdx.x;
    int stride = gridDim.x * 256;
    for (; i < n4; i += stride) {
        float4 v = ((const float4*)src)[i];
        v.x = tf32r(v.x); v.y = tf32r(v.y);
        v.z = tf32r(v.z); v.w = tf32r(v.w);
        ((float4*)dst)[i] = v;
    }
}

// ===========================================================================
// tf32 tensor-core GEMM: Out = X @ W^T. Inputs PRE-ROUNDED to tf32.
// CTA 128x128, BK=32, 2-stage cp.async, 256 threads, 2 CTAs/SM.
// ROUND_OUT: round outputs to tf32 (for tensors feeding later tf32 GEMMs).
// ===========================================================================
#define GM_BK     32
#define GM_PITCH  36
#define GM_STAGE  (128 * GM_PITCH)
#define GM_SMEM_FLOATS (4 * GM_STAGE)
#define GM_SMEM_BYTES  (GM_SMEM_FLOATS * 4)

template <bool ROUND_OUT>
__global__ __launch_bounds__(256, 2) void sgemm_mma(
    const float* __restrict__ X, const float* __restrict__ W,
    float* __restrict__ Out, int N, int K)
{
    extern __shared__ float sm[];
    float* As = sm;
    float* Bs = sm + 2 * GM_STAGE;
    const uint32_t smb = smem_u32(sm);

    const int tid  = threadIdx.x;
    const int wid  = tid >> 5;
    const int lane = tid & 31;
    const int bm   = blockIdx.y * 128;
    const int bn   = blockIdx.x * 128;

    const int wm = (wid & 1) * 64;
    const int wn = (wid >> 1) * 32;

    const int lq = lane >> 2;
    const int lr = lane & 3;

    float d[4][4][4];
#pragma unroll
    for (int mt = 0; mt < 4; mt++)
#pragma unroll
        for (int nt = 0; nt < 4; nt++)
#pragma unroll
            for (int i = 0; i < 4; i++) d[mt][nt][i] = 0.f;

    const int nchunks = K / GM_BK;

    auto load_stage = [&](int chunk) {
        const int s = chunk & 1;
        const int k0 = chunk * GM_BK;
#pragma unroll
        for (int p = 0; p < 4; p++) {
            int idx = tid + 256 * p;
            int row = idx >> 3;
            int c4  = (idx & 7) * 4;
            uint32_t da = smb + (uint32_t)(s * GM_STAGE + row * GM_PITCH + c4) * 4;
            cp16(da, X + (size_t)(bm + row) * K + k0 + c4);
            uint32_t db = smb + (uint32_t)((2 * GM_STAGE) + s * GM_STAGE + row * GM_PITCH + c4) * 4;
            cp16(db, W + (size_t)(bn + row) * K + k0 + c4);
        }
        cp_commit();
    };

    load_stage(0);
    load_stage(1);

    for (int j = 0; j < nchunks; j++) {
        if (j + 1 < nchunks) cp_wait1(); else cp_wait0();
        __syncthreads();

        const int s = j & 1;
        const float* as = As + s * GM_STAGE;
        const float* bs = Bs + s * GM_STAGE;

#pragma unroll
        for (int kk = 0; kk < GM_BK; kk += 8) {
            uint32_t af[4][4], bf[4][2];
#pragma unroll
            for (int mt = 0; mt < 4; mt++) {
                const float* ap = as + (wm + mt * 16 + lq) * GM_PITCH + kk + lr;
                af[mt][0] = __float_as_uint(ap[0]);
                af[mt][1] = __float_as_uint(ap[8 * GM_PITCH]);
                af[mt][2] = __float_as_uint(ap[4]);
                af[mt][3] = __float_as_uint(ap[8 * GM_PITCH + 4]);
            }
#pragma unroll
            for (int nt = 0; nt < 4; nt++) {
                const float* bp = bs + (wn + nt * 8 + lq) * GM_PITCH + kk + lr;
                bf[nt][0] = __float_as_uint(bp[0]);
                bf[nt][1] = __float_as_uint(bp[4]);
            }
#pragma unroll
            for (int mt = 0; mt < 4; mt++)
#pragma unroll
                for (int nt = 0; nt < 4; nt++)
                    mma_tf32(d[mt][nt], af[mt], bf[nt]);
        }
        __syncthreads();
        if (j + 2 < nchunks) load_stage(j + 2);
    }

#pragma unroll
    for (int mt = 0; mt < 4; mt++) {
#pragma unroll
        for (int nt = 0; nt < 4; nt++) {
            int r = bm + wm + mt * 16 + lq;
            int c = bn + wn + nt * 8 + 2 * lr;
            float v0 = d[mt][nt][0], v1 = d[mt][nt][1];
            float v2 = d[mt][nt][2], v3 = d[mt][nt][3];
            if (ROUND_OUT) {
                v0 = tf32r(v0); v1 = tf32r(v1);
                v2 = tf32r(v2); v3 = tf32r(v3);
            }
            *(float2*)(Out + (size_t)r * N + c)       = make_float2(v0, v1);
            *(float2*)(Out + (size_t)(r + 8) * N + c) = make_float2(v2, v3);
        }
    }
}

// ===========================================================================
// mask tile flags
// ===========================================================================
__global__ __launch_bounds__(256) void mask_flags(const int* __restrict__ mask)
{
    const int kt = blockIdx.x & 15;
    const int qt = blockIdx.x >> 4;
    const int tid = threadIdx.x;
    int any0 = 0;
#pragma unroll
    for (int p = 0; p < 16; p++) {
        int lin = (tid + 256 * p) * 4;
        int row = lin >> 7;
        int col = lin & 127;
        int4 m = *(const int4*)(mask + (size_t)(qt * 128 + row) * Sq + kt * 128 + col);
        any0 |= (m.x == 0) | (m.y == 0) | (m.z == 0) | (m.w == 0);
    }
    any0 = __syncthreads_or(any0);
    if (tid == 0) g_maskflag[blockIdx.x] = any0;
}

// ===========================================================================
// Tensor-core flash attention (tf32 mma, pre-rounded Q/K/V inputs).
// ===========================================================================
#define KP 68
#define VP 72
#define PP 132
#define KSTG (128 * KP)
#define VSTG (128 * VP)
#define PWARP (16 * PP)
#define ATT_K_OFF   0
#define ATT_V_OFF   (2 * KSTG)
#define ATT_P_OFF   (2 * KSTG + 2 * VSTG)
#define ATT_SMEM_FLOATS (2 * KSTG + 2 * VSTG + 8 * PWARP)
#define ATT_SMEM_BYTES  (ATT_SMEM_FLOATS * 4)

__global__ __launch_bounds__(256, 1) void attn_mma(
    const float* __restrict__ Q, const float* __restrict__ Kg,
    const float* __restrict__ Vg, const int* __restrict__ mask,
    float* __restrict__ Out)
{
    extern __shared__ float sm[];
    float* Ks = sm + ATT_K_OFF;
    float* Vs = sm + ATT_V_OFF;
    float* Pw = sm + ATT_P_OFF;
    const uint32_t smb = smem_u32(sm);

    const int qt  = blockIdx.x;
    const int qb  = qt * 128;
    const int h   = blockIdx.y;
    const int b   = blockIdx.z;
    const int tid = threadIdx.x;
    const int w   = tid >> 5;
    const int lane = tid & 31;
    const int lq  = lane >> 2;
    const int lr  = lane & 3;

    const size_t base = ((size_t)b * Sq) * Dm + (size_t)h * HDm;
    float* Pme = Pw + w * PWARP;

    auto load_kv = [&](int kb, int s) {
#pragma unroll
        for (int p = 0; p < 8; p++) {
            int idx = tid + 256 * p;
            int row = idx >> 4;
            int c4  = (idx & 15) * 4;
            const float* kp = Kg + base + (size_t)(kb + row) * Dm + c4;
            const float* vp = Vg + base + (size_t)(kb + row) * Dm + c4;
            cp16(smb + (uint32_t)(ATT_V_OFF + s * VSTG + row * VP + c4) * 4, vp);
            cp16(smb + (uint32_t)(ATT_K_OFF + s * KSTG + row * KP + c4) * 4, kp);
        }
        cp_commit();
    };

    {
#pragma unroll
        for (int p = 0; p < 8; p++) {
            int idx = tid + 256 * p;
            int row = idx >> 4;
            int c4  = (idx & 15) * 4;
            cp16(smb + (uint32_t)(ATT_P_OFF + row * KP + c4) * 4,
                 Q + base + (size_t)(qb + row) * Dm + c4);
        }
        cp_commit();
        load_kv(0, 0);
        cp_wait0();
        __syncthreads();
    }

    // Q fragments: q pre-rounded tf32; *0.125f (pow2) keeps tf32 exactness.
    uint32_t qf[8][4];
    {
        const float* qs  = Pw + (w * 16 + lq) * KP;
        const float* qs8 = qs + 8 * KP;
#pragma unroll
        for (int kt = 0; kt < 8; kt++) {
            qf[kt][0] = __float_as_uint(0.125f * qs [kt * 8 + lr]);
            qf[kt][1] = __float_as_uint(0.125f * qs8[kt * 8 + lr]);
            qf[kt][2] = __float_as_uint(0.125f * qs [kt * 8 + lr + 4]);
            qf[kt][3] = __float_as_uint(0.125f * qs8[kt * 8 + lr + 4]);
        }
    }

    float o[8][4];
#pragma unroll
    for (int nt = 0; nt < 8; nt++)
        o[nt][0] = o[nt][1] = o[nt][2] = o[nt][3] = 0.f;
    float m0 = -INFINITY, m1 = -INFINITY, l0 = 0.f, l1 = 0.f;

    const int qrow0 = qb + w * 16 + lq;

    for (int kt_i = 0; kt_i < 16; kt_i++) {
        const int kb = kt_i * 128;
        const int s  = kt_i & 1;
        cp_wait0();
        __syncthreads();
        if (kt_i + 1 < 16) load_kv(kb + 128, s ^ 1);

        const float* ks = Ks + s * KSTG;
        const float* vs = Vs + s * VSTG;

        float d[16][4];
#pragma unroll
        for (int nt = 0; nt < 16; nt++)
            d[nt][0] = d[nt][1] = d[nt][2] = d[nt][3] = 0.f;

#pragma unroll
        for (int kt = 0; kt < 8; kt++) {
            uint32_t bf[16][2];
#pragma unroll
            for (int nt = 0; nt < 16; nt++) {
                const float* bp = ks + (nt * 8 + lq) * KP + kt * 8 + lr;
                bf[nt][0] = __float_as_uint(bp[0]);
                bf[nt][1] = __float_as_uint(bp[4]);
            }
#pragma unroll
            for (int nt = 0; nt < 16; nt++)
                mma_tf32(d[nt], qf[kt], bf[nt]);
        }

        if (g_maskflag[qt * 16 + kt_i]) {
            const int* mr0 = mask + (size_t)qrow0 * Sq + kb + 2 * lr;
            const int* mr1 = mr0 + 8 * Sq;
#pragma unroll
            for (int nt = 0; nt < 16; nt++) {
                int2 a = *(const int2*)(mr0 + nt * 8);
                int2 c = *(const int2*)(mr1 + nt * 8);
                if (a.x == 0) d[nt][0] = -1e9f;
                if (a.y == 0) d[nt][1] = -1e9f;
                if (c.x == 0) d[nt][2] = -1e9f;
                if (c.y == 0) d[nt][3] = -1e9f;
            }
        }

        float mx0 = -INFINITY, mx1 = -INFINITY;
#pragma unroll
        for (int nt = 0; nt < 16; nt++) {
            mx0 = fmaxf(mx0, fmaxf(d[nt][0], d[nt][1]));
            mx1 = fmaxf(mx1, fmaxf(d[nt][2], d[nt][3]));
        }
        mx0 = fmaxf(mx0, __shfl_xor_sync(0xffffffffu, mx0, 1));
        mx0 = fmaxf(mx0, __shfl_xor_sync(0xffffffffu, mx0, 2));
        mx1 = fmaxf(mx1, __shfl_xor_sync(0xffffffffu, mx1, 1));
        mx1 = fmaxf(mx1, __shfl_xor_sync(0xffffffffu, mx1, 2));

        float mn0 = fmaxf(m0, mx0), mn1 = fmaxf(m1, mx1);
        float al0 = __expf(m0 - mn0), al1 = __expf(m1 - mn1);
        m0 = mn0; m1 = mn1;

        float rs0 = 0.f, rs1 = 0.f;
#pragma unroll
        for (int nt = 0; nt < 16; nt++) {
            float p0 = __expf(d[nt][0] - mn0);
            float p1 = __expf(d[nt][1] - mn0);
            float p2 = __expf(d[nt][2] - mn1);
            float p3 = __expf(d[nt][3] - mn1);
            rs0 += p0 + p1; rs1 += p2 + p3;
            *(float2*)&Pme[lq * PP + nt * 8 + 2 * lr]       = make_float2(p0, p1);
            *(float2*)&Pme[(lq + 8) * PP + nt * 8 + 2 * lr] = make_float2(p2, p3);
        }
        rs0 += __shfl_xor_sync(0xffffffffu, rs0, 1);
        rs0 += __shfl_xor_sync(0xffffffffu, rs0, 2);
        rs1 += __shfl_xor_sync(0xffffffffu, rs1, 1);
        rs1 += __shfl_xor_sync(0xffffffffu, rs1, 2);
        l0 = l0 * al0 + rs0;
        l1 = l1 * al1 + rs1;

#pragma unroll
        for (int nt = 0; nt < 8; nt++) {
            o[nt][0] *= al0; o[nt][1] *= al0;
            o[nt][2] *= al1; o[nt][3] *= al1;
        }
        __syncwarp();

#pragma unroll
        for (int kt = 0; kt < 16; kt++) {
            uint32_t af[4];
            af[0] = f2tf32(Pme[lq * PP + kt * 8 + lr]);
            af[1] = f2tf32(Pme[(lq + 8) * PP + kt * 8 + lr]);
            af[2] = f2tf32(Pme[lq * PP + kt * 8 + lr + 4]);
            af[3] = f2tf32(Pme[(lq + 8) * PP + kt * 8 + lr + 4]);
            const float* v0 = vs + (kt * 8 + lr) * VP + lq;
            const float* v4 = v0 + 4 * VP;
#pragma unroll
            for (int nt = 0; nt < 8; nt++) {
                uint32_t bf[2];
                bf[0] = __float_as_uint(v0[nt * 8]);
                bf[1] = __float_as_uint(v4[nt * 8]);
                mma_tf32(o[nt], af, bf);
            }
        }
        __syncwarp();
    }

    // epilogue: divide, ROUND to tf32 (feeds final tf32 GEMM), store
    float inv0 = 1.f / l0, inv1 = 1.f / l1;
    float* out0 = Out + base + (size_t)qrow0 * Dm;
    float* out1 = out0 + (size_t)8 * Dm;
#pragma unroll
    for (int nt = 0; nt < 8; nt++) {
        *(float2*)(out0 + nt * 8 + 2 * lr) =
            make_float2(tf32r(o[nt][0] * inv0), tf32r(o[nt][1] * inv0));
        *(float2*)(out1 + nt * 8 + 2 * lr) =
            make_float2(tf32r(o[nt][2] * inv1), tf32r(o[nt][3] * inv1));
    }
}

// ===========================================================================
extern "C" void kernel_launch(void* const* d_in, const int* in_sizes, int n_in,
                              void* d_out, int out_size)
{
    (void)in_sizes; (void)n_in; (void)out_size;
    const float* query = (const float*)d_in[0];
    const float* key_  = (const float*)d_in[1];
    const float* value = (const float*)d_in[2];
    const int*   mask  = (const int*)d_in[3];
    const float* w_q   = (const float*)d_in[4];
    const float* w_k   = (const float*)d_in[5];
    const float* w_v   = (const float*)d_in[6];
    const float* w_o   = (const float*)d_in[7];
    float* out = (float*)d_out;

    float *q, *k, *v, *attn, *xq, *xk, *xv, *wq, *wk, *wv, *wo;
    cudaGetSymbolAddress((void**)&q,    g_q);
    cudaGetSymbolAddress((void**)&k,    g_k);
    cudaGetSymbolAddress((void**)&v,    g_v);
    cudaGetSymbolAddress((void**)&attn, g_attn);
    cudaGetSymbolAddress((void**)&xq,   g_xq);
    cudaGetSymbolAddress((void**)&xk,   g_xk);
    cudaGetSymbolAddress((void**)&xv,   g_xv);
    cudaGetSymbolAddress((void**)&wq,   g_wq);
    cudaGetSymbolAddress((void**)&wk,   g_wk);
    cudaGetSymbolAddress((void**)&wv,   g_wv);
    cudaGetSymbolAddress((void**)&wo,   g_wo);

    cudaFuncSetAttribute(sgemm_mma<true>,
                         cudaFuncAttributeMaxDynamicSharedMemorySize, GM_SMEM_BYTES);
    cudaFuncSetAttribute(sgemm_mma<false>,
                         cudaFuncAttributeMaxDynamicSharedMemorySize, GM_SMEM_BYTES);
    cudaFuncSetAttribute(attn_mma,
                         cudaFuncAttributeMaxDynamicSharedMemorySize, ATT_SMEM_BYTES);

    const int NX4 = (Mrows * Dm) / 4;   // 2M float4
    const int NW4 = (Dm * Dm) / 4;      // 256K float4
    tf32_round_k<<<592, 256>>>(query, xq, NX4);
    tf32_round_k<<<592, 256>>>(key_,  xk, NX4);
    tf32_round_k<<<592, 256>>>(value, xv, NX4);
    tf32_round_k<<<296, 256>>>(w_q, wq, NW4);
    tf32_round_k<<<296, 256>>>(w_k, wk, NW4);
    tf32_round_k<<<296, 256>>>(w_v, wv, NW4);
    tf32_round_k<<<296, 256>>>(w_o, wo, NW4);
    mask_flags<<<256, 256>>>(mask);

    dim3 gg(Dm / 128, Mrows / 128);   // (8, 64)
    sgemm_mma<true><<<gg, 256, GM_SMEM_BYTES>>>(xq, wq, q, Dm, Dm);
    sgemm_mma<true><<<gg, 256, GM_SMEM_BYTES>>>(xk, wk, k, Dm, Dm);
    sgemm_mma<true><<<gg, 256, GM_SMEM_BYTES>>>(xv, wv, v, Dm, Dm);

    dim3 ga(Sq / 128, Hn, Bsz);       // (16, 16, 4)
    attn_mma<<<ga, 256, ATT_SMEM_BYTES>>>(q, k, v, mask, attn);

    sgemm_mma<false><<<gg, 256, GM_SMEM_BYTES>>>(attn, wo, out, Dm, Dm);
}

// round 6
// speedup vs baseline: 3.7115x; 1.0695x over previous
#include <cuda_runtime.h>
#include <math.h>
#include <stdint.h>

#define Bsz 4
#define Sq  2048
#define Dm  1024
#define Hn  16
#define HDm 64
#define Mrows (Bsz * Sq)   // 8192

// Scratch (device globals — no allocation in kernel_launch)
__device__ float g_q[(size_t)Mrows * Dm];
__device__ float g_k[(size_t)Mrows * Dm];
__device__ float g_v[(size_t)Mrows * Dm];
__device__ float g_attn[(size_t)Mrows * Dm];
__device__ float g_xq[(size_t)Mrows * Dm];
__device__ float g_xk[(size_t)Mrows * Dm];
__device__ float g_xv[(size_t)Mrows * Dm];
__device__ float g_wq[(size_t)Dm * Dm];
__device__ float g_wk[(size_t)Dm * Dm];
__device__ float g_wv[(size_t)Dm * Dm];
__device__ float g_wo[(size_t)Dm * Dm];
__device__ int   g_maskflag[512];     // [qtile(16)][ktile(32)]

// ===========================================================================
// helpers
// ===========================================================================
static __device__ __forceinline__ uint32_t smem_u32(const void* p) {
    uint32_t a;
    asm("{ .reg .u64 t; cvta.to.shared.u64 t, %1; cvt.u32.u64 %0, t; }"
        : "=r"(a) : "l"(p));
    return a;
}

static __device__ __forceinline__ void cp16(uint32_t dst, const void* src) {
    asm volatile("cp.async.cg.shared.global [%0], [%1], 16;"
                 :: "r"(dst), "l"(src) : "memory");
}
static __device__ __forceinline__ void cp_commit() {
    asm volatile("cp.async.commit_group;" ::: "memory");
}
static __device__ __forceinline__ void cp_wait1() {
    asm volatile("cp.async.wait_group 1;" ::: "memory");
}
static __device__ __forceinline__ void cp_wait0() {
    asm volatile("cp.async.wait_group 0;" ::: "memory");
}

static __device__ __forceinline__ uint32_t f2tf32(float f) {
    uint32_t u;
    asm("cvt.rna.tf32.f32 %0, %1;" : "=r"(u) : "f"(f));
    return u;
}
static __device__ __forceinline__ float tf32r(float f) {
    return __uint_as_float(f2tf32(f));
}

// D(16x8,f32) += A(16x8,tf32,row) * B(8x8,tf32,col)
static __device__ __forceinline__ void mma_tf32(
    float* d, const uint32_t* a, const uint32_t* b)
{
    asm volatile(
        "mma.sync.aligned.m16n8k8.row.col.f32.tf32.tf32.f32 "
        "{%0,%1,%2,%3}, {%4,%5,%6,%7}, {%8,%9}, {%0,%1,%2,%3};"
        : "+f"(d[0]), "+f"(d[1]), "+f"(d[2]), "+f"(d[3])
        : "r"(a[0]), "r"(a[1]), "r"(a[2]), "r"(a[3]),
          "r"(b[0]), "r"(b[1]));
}

// ===========================================================================
// elementwise tf32 pre-round (merged variants)
// ===========================================================================
__global__ __launch_bounds__(256) void tf32_round3(
    const float* __restrict__ s0, const float* __restrict__ s1,
    const float* __restrict__ s2,
    float* __restrict__ d0, float* __restrict__ d1, float* __restrict__ d2,
    int n4)
{
    const float* src = (blockIdx.z == 0) ? s0 : (blockIdx.z == 1) ? s1 : s2;
    float*       dst = (blockIdx.z == 0) ? d0 : (blockIdx.z == 1) ? d1 : d2;
    int i = blockIdx.x * 256 + threadIdx.x;
    int stride = gridDim.x * 256;
    for (; i < n4; i += stride) {
        float4 v = ((const float4*)src)[i];
        v.x = tf32r(v.x); v.y = tf32r(v.y);
        v.z = tf32r(v.z); v.w = tf32r(v.w);
        ((float4*)dst)[i] = v;
    }
}

__global__ __launch_bounds__(256) void tf32_round4(
    const float* __restrict__ s0, const float* __restrict__ s1,
    const float* __restrict__ s2, const float* __restrict__ s3,
    float* __restrict__ d0, float* __restrict__ d1,
    float* __restrict__ d2, float* __restrict__ d3,
    int n4)
{
    const float* src = (blockIdx.z == 0) ? s0 : (blockIdx.z == 1) ? s1
                     : (blockIdx.z == 2) ? s2 : s3;
    float*       dst = (blockIdx.z == 0) ? d0 : (blockIdx.z == 1) ? d1
                     : (blockIdx.z == 2) ? d2 : d3;
    int i = blockIdx.x * 256 + threadIdx.x;
    int stride = gridDim.x * 256;
    for (; i < n4; i += stride) {
        float4 v = ((const float4*)src)[i];
        v.x = tf32r(v.x); v.y = tf32r(v.y);
        v.z = tf32r(v.z); v.w = tf32r(v.w);
        ((float4*)dst)[i] = v;
    }
}

// ===========================================================================
// tf32 GEMM core (pre-rounded inputs). CTA 128x128, BK=32, 2-stage, occ 2.
// ===========================================================================
#define GM_BK     32
#define GM_PITCH  36
#define GM_STAGE  (128 * GM_PITCH)
#define GM_SMEM_FLOATS (4 * GM_STAGE)
#define GM_SMEM_BYTES  (GM_SMEM_FLOATS * 4)

template <bool ROUND_OUT>
static __device__ __forceinline__ void gemm_body(
    const float* __restrict__ X, const float* __restrict__ W,
    float* __restrict__ Out, int N, int K)
{
    extern __shared__ float sm[];
    float* As = sm;
    float* Bs = sm + 2 * GM_STAGE;
    const uint32_t smb = smem_u32(sm);

    const int tid  = threadIdx.x;
    const int wid  = tid >> 5;
    const int lane = tid & 31;
    const int bm   = blockIdx.y * 128;
    const int bn   = blockIdx.x * 128;

    const int wm = (wid & 1) * 64;
    const int wn = (wid >> 1) * 32;

    const int lq = lane >> 2;
    const int lr = lane & 3;

    float d[4][4][4];
#pragma unroll
    for (int mt = 0; mt < 4; mt++)
#pragma unroll
        for (int nt = 0; nt < 4; nt++)
#pragma unroll
            for (int i = 0; i < 4; i++) d[mt][nt][i] = 0.f;

    const int nchunks = K / GM_BK;

    auto load_stage = [&](int chunk) {
        const int s = chunk & 1;
        const int k0 = chunk * GM_BK;
#pragma unroll
        for (int p = 0; p < 4; p++) {
            int idx = tid + 256 * p;
            int row = idx >> 3;
            int c4  = (idx & 7) * 4;
            uint32_t da = smb + (uint32_t)(s * GM_STAGE + row * GM_PITCH + c4) * 4;
            cp16(da, X + (size_t)(bm + row) * K + k0 + c4);
            uint32_t db = smb + (uint32_t)((2 * GM_STAGE) + s * GM_STAGE + row * GM_PITCH + c4) * 4;
            cp16(db, W + (size_t)(bn + row) * K + k0 + c4);
        }
        cp_commit();
    };

    load_stage(0);
    load_stage(1);

    for (int j = 0; j < nchunks; j++) {
        if (j + 1 < nchunks) cp_wait1(); else cp_wait0();
        __syncthreads();

        const int s = j & 1;
        const float* as = As + s * GM_STAGE;
        const float* bs = Bs + s * GM_STAGE;

#pragma unroll
        for (int kk = 0; kk < GM_BK; kk += 8) {
            uint32_t af[4][4], bf[4][2];
#pragma unroll
            for (int mt = 0; mt < 4; mt++) {
                const float* ap = as + (wm + mt * 16 + lq) * GM_PITCH + kk + lr;
                af[mt][0] = __float_as_uint(ap[0]);
                af[mt][1] = __float_as_uint(ap[8 * GM_PITCH]);
                af[mt][2] = __float_as_uint(ap[4]);
                af[mt][3] = __float_as_uint(ap[8 * GM_PITCH + 4]);
            }
#pragma unroll
            for (int nt = 0; nt < 4; nt++) {
                const float* bp = bs + (wn + nt * 8 + lq) * GM_PITCH + kk + lr;
                bf[nt][0] = __float_as_uint(bp[0]);
                bf[nt][1] = __float_as_uint(bp[4]);
            }
#pragma unroll
            for (int mt = 0; mt < 4; mt++)
#pragma unroll
                for (int nt = 0; nt < 4; nt++)
                    mma_tf32(d[mt][nt], af[mt], bf[nt]);
        }
        __syncthreads();
        if (j + 2 < nchunks) load_stage(j + 2);
    }

#pragma unroll
    for (int mt = 0; mt < 4; mt++) {
#pragma unroll
        for (int nt = 0; nt < 4; nt++) {
            int r = bm + wm + mt * 16 + lq;
            int c = bn + wn + nt * 8 + 2 * lr;
            float v0 = d[mt][nt][0], v1 = d[mt][nt][1];
            float v2 = d[mt][nt][2], v3 = d[mt][nt][3];
            if (ROUND_OUT) {
                v0 = tf32r(v0); v1 = tf32r(v1);
                v2 = tf32r(v2); v3 = tf32r(v3);
            }
            *(float2*)(Out + (size_t)r * N + c)       = make_float2(v0, v1);
            *(float2*)(Out + (size_t)(r + 8) * N + c) = make_float2(v2, v3);
        }
    }
}

// merged Q/K/V projection launch: blockIdx.z selects tensor
__global__ __launch_bounds__(256, 2) void sgemm_qkv(
    const float* __restrict__ x0, const float* __restrict__ x1,
    const float* __restrict__ x2,
    const float* __restrict__ w0, const float* __restrict__ w1,
    const float* __restrict__ w2,
    float* __restrict__ o0, float* __restrict__ o1, float* __restrict__ o2)
{
    const float* X = (blockIdx.z == 0) ? x0 : (blockIdx.z == 1) ? x1 : x2;
    const float* W = (blockIdx.z == 0) ? w0 : (blockIdx.z == 1) ? w1 : w2;
    float*       O = (blockIdx.z == 0) ? o0 : (blockIdx.z == 1) ? o1 : o2;
    gemm_body<true>(X, W, O, Dm, Dm);
}

__global__ __launch_bounds__(256, 2) void sgemm_out(
    const float* __restrict__ X, const float* __restrict__ W,
    float* __restrict__ Out)
{
    gemm_body<false>(X, W, Out, Dm, Dm);
}

// ===========================================================================
// mask tile flags: 128q x 64k tiles
// ===========================================================================
__global__ __launch_bounds__(256) void mask_flags(const int* __restrict__ mask)
{
    const int kt = blockIdx.x & 31;
    const int qt = blockIdx.x >> 5;
    const int tid = threadIdx.x;
    int any0 = 0;
#pragma unroll
    for (int p = 0; p < 8; p++) {
        int lin = (tid + 256 * p) * 4;       // 0..8188
        int row = lin >> 6;                  // 0..127
        int col = lin & 63;
        int4 m = *(const int4*)(mask + (size_t)(qt * 128 + row) * Sq + kt * 64 + col);
        any0 |= (m.x == 0) | (m.y == 0) | (m.z == 0) | (m.w == 0);
    }
    any0 = __syncthreads_or(any0);
    if (tid == 0) g_maskflag[blockIdx.x] = any0;
}

// ===========================================================================
// Tensor-core flash attention, 64-key tiles, 2 CTAs/SM.
// CTA = (128 q-rows, h, b), 8 warps; warp w owns rows [16w,16w+16).
// ===========================================================================
#define KP 68
#define VP 72
#define PP 68
#define KSTG (64 * KP)                       // 4352
#define VSTG (64 * VP)                       // 4608
#define PWARP (16 * PP)                      // 1088
#define ATT_K_OFF   0
#define ATT_V_OFF   (2 * KSTG)               // 8704
#define ATT_P_OFF   (2 * KSTG + 2 * VSTG)    // 17920
#define ATT_SMEM_FLOATS (2 * KSTG + 2 * VSTG + 8 * PWARP)   // 26624
#define ATT_SMEM_BYTES  (ATT_SMEM_FLOATS * 4)               // 106496

__global__ __launch_bounds__(256, 2) void attn_mma(
    const float* __restrict__ Q, const float* __restrict__ Kg,
    const float* __restrict__ Vg, const int* __restrict__ mask,
    float* __restrict__ Out)
{
    extern __shared__ float sm[];
    float* Ks = sm + ATT_K_OFF;
    float* Vs = sm + ATT_V_OFF;
    float* Pw = sm + ATT_P_OFF;
    const uint32_t smb = smem_u32(sm);

    const int qt  = blockIdx.x;
    const int qb  = qt * 128;
    const int h   = blockIdx.y;
    const int b   = blockIdx.z;
    const int tid = threadIdx.x;
    const int w   = tid >> 5;
    const int lane = tid & 31;
    const int lq  = lane >> 2;
    const int lr  = lane & 3;

    const size_t base = ((size_t)b * Sq) * Dm + (size_t)h * HDm;
    float* Pme = Pw + w * PWARP;

    // 64-key K/V tile -> buffer s
    auto load_kv = [&](int kb, int s) {
#pragma unroll
        for (int p = 0; p < 4; p++) {
            int idx = tid + 256 * p;           // 0..1023
            int row = idx >> 4;                // 0..63
            int c4  = (idx & 15) * 4;          // 0..60
            const float* kp = Kg + base + (size_t)(kb + row) * Dm + c4;
            const float* vp = Vg + base + (size_t)(kb + row) * Dm + c4;
            cp16(smb + (uint32_t)(ATT_V_OFF + s * VSTG + row * VP + c4) * 4, vp);
            cp16(smb + (uint32_t)(ATT_K_OFF + s * KSTG + row * KP + c4) * 4, kp);
        }
        cp_commit();
    };

    // prologue: Q tile (128x64) into P area (pitch PP=68), K/V tile 0
    {
#pragma unroll
        for (int p = 0; p < 8; p++) {
            int idx = tid + 256 * p;
            int row = idx >> 4;
            int c4  = (idx & 15) * 4;
            cp16(smb + (uint32_t)(ATT_P_OFF + row * PP + c4) * 4,
                 Q + base + (size_t)(qb + row) * Dm + c4);
        }
        cp_commit();
        load_kv(0, 0);
        cp_wait0();
        __syncthreads();
    }

    // Q fragments (pre-rounded input; *0.125f pow2-exact)
    uint32_t qf[8][4];
    {
        const float* qs  = Pw + (w * 16 + lq) * PP;
        const float* qs8 = qs + 8 * PP;
#pragma unroll
        for (int kt = 0; kt < 8; kt++) {
            qf[kt][0] = __float_as_uint(0.125f * qs [kt * 8 + lr]);
            qf[kt][1] = __float_as_uint(0.125f * qs8[kt * 8 + lr]);
            qf[kt][2] = __float_as_uint(0.125f * qs [kt * 8 + lr + 4]);
            qf[kt][3] = __float_as_uint(0.125f * qs8[kt * 8 + lr + 4]);
        }
    }
    __syncthreads();   // everyone has Q frags before P area reuse

    float o[8][4];
#pragma unroll
    for (int nt = 0; nt < 8; nt++)
        o[nt][0] = o[nt][1] = o[nt][2] = o[nt][3] = 0.f;
    float m0 = -INFINITY, m1 = -INFINITY, l0 = 0.f, l1 = 0.f;

    const int qrow0 = qb + w * 16 + lq;

    for (int kt_i = 0; kt_i < 32; kt_i++) {
        const int kb = kt_i * 64;
        const int s  = kt_i & 1;
        cp_wait0();
        __syncthreads();
        if (kt_i + 1 < 32) load_kv(kb + 64, s ^ 1);

        const float* ks = Ks + s * KSTG;
        const float* vs = Vs + s * VSTG;

        // S = Q @ K^T : 8 n-tiles (64 keys)
        float d[8][4];
#pragma unroll
        for (int nt = 0; nt < 8; nt++)
            d[nt][0] = d[nt][1] = d[nt][2] = d[nt][3] = 0.f;

#pragma unroll
        for (int kt = 0; kt < 8; kt++) {
            uint32_t bf[8][2];
#pragma unroll
            for (int nt = 0; nt < 8; nt++) {
                const float* bp = ks + (nt * 8 + lq) * KP + kt * 8 + lr;
                bf[nt][0] = __float_as_uint(bp[0]);
                bf[nt][1] = __float_as_uint(bp[4]);
            }
#pragma unroll
            for (int nt = 0; nt < 8; nt++)
                mma_tf32(d[nt], qf[kt], bf[nt]);
        }

        if (g_maskflag[qt * 32 + kt_i]) {
            const int* mr0 = mask + (size_t)qrow0 * Sq + kb + 2 * lr;
            const int* mr1 = mr0 + 8 * Sq;
#pragma unroll
            for (int nt = 0; nt < 8; nt++) {
                int2 a = *(const int2*)(mr0 + nt * 8);
                int2 c = *(const int2*)(mr1 + nt * 8);
                if (a.x == 0) d[nt][0] = -1e9f;
                if (a.y == 0) d[nt][1] = -1e9f;
                if (c.x == 0) d[nt][2] = -1e9f;
                if (c.y == 0) d[nt][3] = -1e9f;
            }
        }

        // online softmax, rows lq / lq+8, reduce over quad
        float mx0 = -INFINITY, mx1 = -INFINITY;
#pragma unroll
        for (int nt = 0; nt < 8; nt++) {
            mx0 = fmaxf(mx0, fmaxf(d[nt][0], d[nt][1]));
            mx1 = fmaxf(mx1, fmaxf(d[nt][2], d[nt][3]));
        }
        mx0 = fmaxf(mx0, __shfl_xor_sync(0xffffffffu, mx0, 1));
        mx0 = fmaxf(mx0, __shfl_xor_sync(0xffffffffu, mx0, 2));
        mx1 = fmaxf(mx1, __shfl_xor_sync(0xffffffffu, mx1, 1));
        mx1 = fmaxf(mx1, __shfl_xor_sync(0xffffffffu, mx1, 2));

        float mn0 = fmaxf(m0, mx0), mn1 = fmaxf(m1, mx1);
        float al0 = __expf(m0 - mn0), al1 = __expf(m1 - mn1);
        m0 = mn0; m1 = mn1;

        float rs0 = 0.f, rs1 = 0.f;
#pragma unroll
        for (int nt = 0; nt < 8; nt++) {
            float p0 = __expf(d[nt][0] - mn0);
            float p1 = __expf(d[nt][1] - mn0);
            float p2 = __expf(d[nt][2] - mn1);
            float p3 = __expf(d[nt][3] - mn1);
            rs0 += p0 + p1; rs1 += p2 + p3;
            *(float2*)&Pme[lq * PP + nt * 8 + 2 * lr]       = make_float2(p0, p1);
            *(float2*)&Pme[(lq + 8) * PP + nt * 8 + 2 * lr] = make_float2(p2, p3);
        }
        rs0 += __shfl_xor_sync(0xffffffffu, rs0, 1);
        rs0 += __shfl_xor_sync(0xffffffffu, rs0, 2);
        rs1 += __shfl_xor_sync(0xffffffffu, rs1, 1);
        rs1 += __shfl_xor_sync(0xffffffffu, rs1, 2);
        l0 = l0 * al0 + rs0;
        l1 = l1 * al1 + rs1;

#pragma unroll
        for (int nt = 0; nt < 8; nt++) {
            o[nt][0] *= al0; o[nt][1] *= al0;
            o[nt][2] *= al1; o[nt][3] *= al1;
        }
        __syncwarp();

        // O += P @ V : 8 k-steps (64 keys) x 8 n-tiles (64 dims)
#pragma unroll
        for (int kt = 0; kt < 8; kt++) {
            uint32_t af[4];
            af[0] = f2tf32(Pme[lq * PP + kt * 8 + lr]);
            af[1] = f2tf32(Pme[(lq + 8) * PP + kt * 8 + lr]);
            af[2] = f2tf32(Pme[lq * PP + kt * 8 + lr + 4]);
            af[3] = f2tf32(Pme[(lq + 8) * PP + kt * 8 + lr + 4]);
            const float* v0 = vs + (kt * 8 + lr) * VP + lq;
            const float* v4 = v0 + 4 * VP;
#pragma unroll
            for (int nt = 0; nt < 8; nt++) {
                uint32_t bf[2];
                bf[0] = __float_as_uint(v0[nt * 8]);
                bf[1] = __float_as_uint(v4[nt * 8]);
                mma_tf32(o[nt], af, bf);
            }
        }
        __syncwarp();
    }

    // epilogue: divide, round to tf32 (feeds final tf32 GEMM), store
    float inv0 = 1.f / l0, inv1 = 1.f / l1;
    float* out0 = Out + base + (size_t)qrow0 * Dm;
    float* out1 = out0 + (size_t)8 * Dm;
#pragma unroll
    for (int nt = 0; nt < 8; nt++) {
        *(float2*)(out0 + nt * 8 + 2 * lr) =
            make_float2(tf32r(o[nt][0] * inv0), tf32r(o[nt][1] * inv0));
        *(float2*)(out1 + nt * 8 + 2 * lr) =
            make_float2(tf32r(o[nt][2] * inv1), tf32r(o[nt][3] * inv1));
    }
}

// ===========================================================================
extern "C" void kernel_launch(void* const* d_in, const int* in_sizes, int n_in,
                              void* d_out, int out_size)
{
    (void)in_sizes; (void)n_in; (void)out_size;
    const float* query = (const float*)d_in[0];
    const float* key_  = (const float*)d_in[1];
    const float* value = (const float*)d_in[2];
    const int*   mask  = (const int*)d_in[3];
    const float* w_q   = (const float*)d_in[4];
    const float* w_k   = (const float*)d_in[5];
    const float* w_v   = (const float*)d_in[6];
    const float* w_o   = (const float*)d_in[7];
    float* out = (float*)d_out;

    float *q, *k, *v, *attn, *xq, *xk, *xv, *wq, *wk, *wv, *wo;
    cudaGetSymbolAddress((void**)&q,    g_q);
    cudaGetSymbolAddress((void**)&k,    g_k);
    cudaGetSymbolAddress((void**)&v,    g_v);
    cudaGetSymbolAddress((void**)&attn, g_attn);
    cudaGetSymbolAddress((void**)&xq,   g_xq);
    cudaGetSymbolAddress((void**)&xk,   g_xk);
    cudaGetSymbolAddress((void**)&xv,   g_xv);
    cudaGetSymbolAddress((void**)&wq,   g_wq);
    cudaGetSymbolAddress((void**)&wk,   g_wk);
    cudaGetSymbolAddress((void**)&wv,   g_wv);
    cudaGetSymbolAddress((void**)&wo,   g_wo);

    cudaFuncSetAttribute(sgemm_qkv,
                         cudaFuncAttributeMaxDynamicSharedMemorySize, GM_SMEM_BYTES);
    cudaFuncSetAttribute(sgemm_out,
                         cudaFuncAttributeMaxDynamicSharedMemorySize, GM_SMEM_BYTES);
    cudaFuncSetAttribute(attn_mma,
                         cudaFuncAttributeMaxDynamicSharedMemorySize, ATT_SMEM_BYTES);

    const int NX4 = (Mrows * Dm) / 4;
    const int NW4 = (Dm * Dm) / 4;
    tf32_round3<<<dim3(296, 1, 3), 256>>>(query, key_, value, xq, xk, xv, NX4);
    tf32_round4<<<dim3(148, 1, 4), 256>>>(w_q, w_k, w_v, w_o, wq, wk, wv, wo, NW4);
    mask_flags<<<512, 256>>>(mask);

    dim3 gqkv(Dm / 128, Mrows / 128, 3);   // (8, 64, 3)
    sgemm_qkv<<<gqkv, 256, GM_SMEM_BYTES>>>(xq, xk, xv, wq, wk, wv, q, k, v);

    dim3 ga(Sq / 128, Hn, Bsz);            // (16, 16, 4)
    attn_mma<<<ga, 256, ATT_SMEM_BYTES>>>(q, k, v, mask, attn);

    dim3 gg(Dm / 128, Mrows / 128);        // (8, 64)
    sgemm_out<<<gg, 256, GM_SMEM_BYTES>>>(attn, wo, out);
}

// round 7
// speedup vs baseline: 6.9813x; 1.8810x over previous
#include <cuda_runtime.h>
#include <cuda_fp16.h>
#include <math.h>
#include <stdint.h>

#define Bsz 4
#define Sq  2048
#define Dm  1024
#define Hn  16
#define HDm 64
#define Mrows (Bsz * Sq)   // 8192

// Scratch (device globals — no allocation in kernel_launch)
__device__ __half g_q[(size_t)Mrows * Dm];
__device__ __half g_k[(size_t)Mrows * Dm];
__device__ __half g_v[(size_t)Mrows * Dm];
__device__ __half g_attn[(size_t)Mrows * Dm];
__device__ __half g_xq[(size_t)Mrows * Dm];
__device__ __half g_xk[(size_t)Mrows * Dm];
__device__ __half g_xv[(size_t)Mrows * Dm];
__device__ __half g_wq[(size_t)Dm * Dm];
__device__ __half g_wk[(size_t)Dm * Dm];
__device__ __half g_wv[(size_t)Dm * Dm];
__device__ __half g_wo[(size_t)Dm * Dm];
__device__ int    g_maskflag[512];    // [qtile(16)][ktile(32)]

// ===========================================================================
// helpers
// ===========================================================================
static __device__ __forceinline__ uint32_t smem_u32(const void* p) {
    uint32_t a;
    asm("{ .reg .u64 t; cvta.to.shared.u64 t, %1; cvt.u32.u64 %0, t; }"
        : "=r"(a) : "l"(p));
    return a;
}

static __device__ __forceinline__ void cp16(uint32_t dst, const void* src) {
    asm volatile("cp.async.cg.shared.global [%0], [%1], 16;"
                 :: "r"(dst), "l"(src) : "memory");
}
static __device__ __forceinline__ void cp_commit() {
    asm volatile("cp.async.commit_group;" ::: "memory");
}
static __device__ __forceinline__ void cp_wait1() {
    asm volatile("cp.async.wait_group 1;" ::: "memory");
}
static __device__ __forceinline__ void cp_wait0() {
    asm volatile("cp.async.wait_group 0;" ::: "memory");
}

static __device__ __forceinline__ uint32_t h2u(__half2 h) {
    uint32_t u;
    __builtin_memcpy(&u, &h, 4);
    return u;
}

// D(16x8,f32) += A(16x16,f16,row) * B(16x8,f16,col)
static __device__ __forceinline__ void mma_f16(
    float* d, const uint32_t* a, uint32_t b0, uint32_t b1)
{
    asm volatile(
        "mma.sync.aligned.m16n8k16.row.col.f32.f16.f16.f32 "
        "{%0,%1,%2,%3}, {%4,%5,%6,%7}, {%8,%9}, {%0,%1,%2,%3};"
        : "+f"(d[0]), "+f"(d[1]), "+f"(d[2]), "+f"(d[3])
        : "r"(a[0]), "r"(a[1]), "r"(a[2]), "r"(a[3]),
          "r"(b0), "r"(b1));
}

// ldmatrix x4 transposed (for V as PV B-operand)
static __device__ __forceinline__ void ldsm_x4_t(
    uint32_t& b0, uint32_t& b1, uint32_t& b2, uint32_t& b3, uint32_t addr)
{
    asm volatile(
        "ldmatrix.sync.aligned.m8n8.x4.trans.shared.b16 {%0,%1,%2,%3}, [%4];"
        : "=r"(b0), "=r"(b1), "=r"(b2), "=r"(b3) : "r"(addr));
}

// ===========================================================================
// fp32 -> fp16 conversion (merged variants)
// ===========================================================================
__global__ __launch_bounds__(256) void h_conv3(
    const float* __restrict__ s0, const float* __restrict__ s1,
    const float* __restrict__ s2,
    __half* __restrict__ d0, __half* __restrict__ d1, __half* __restrict__ d2,
    int n4)
{
    const float* src = (blockIdx.z == 0) ? s0 : (blockIdx.z == 1) ? s1 : s2;
    __half*      dst = (blockIdx.z == 0) ? d0 : (blockIdx.z == 1) ? d1 : d2;
    int i = blockIdx.x * 256 + threadIdx.x;
    int stride = gridDim.x * 256;
    for (; i < n4; i += stride) {
        float4 v = ((const float4*)src)[i];
        __half2 h0 = __floats2half2_rn(v.x, v.y);
        __half2 h1 = __floats2half2_rn(v.z, v.w);
        uint2 u;
        u.x = h2u(h0); u.y = h2u(h1);
        ((uint2*)dst)[i] = u;
    }
}

__global__ __launch_bounds__(256) void h_conv4(
    const float* __restrict__ s0, const float* __restrict__ s1,
    const float* __restrict__ s2, const float* __restrict__ s3,
    __half* __restrict__ d0, __half* __restrict__ d1,
    __half* __restrict__ d2, __half* __restrict__ d3,
    int n4)
{
    const float* src = (blockIdx.z == 0) ? s0 : (blockIdx.z == 1) ? s1
                     : (blockIdx.z == 2) ? s2 : s3;
    __half*      dst = (blockIdx.z == 0) ? d0 : (blockIdx.z == 1) ? d1
                     : (blockIdx.z == 2) ? d2 : d3;
    int i = blockIdx.x * 256 + threadIdx.x;
    int stride = gridDim.x * 256;
    for (; i < n4; i += stride) {
        float4 v = ((const float4*)src)[i];
        __half2 h0 = __floats2half2_rn(v.x, v.y);
        __half2 h1 = __floats2half2_rn(v.z, v.w);
        uint2 u;
        u.x = h2u(h0); u.y = h2u(h1);
        ((uint2*)dst)[i] = u;
    }
}

// ===========================================================================
// fp16 GEMM: Out[M][N] = X[M][K] @ W[N][K]^T, f32 accum.
// CTA 128x128, BK=64 halves, 2-stage cp.async, 256 threads, occ 2.
// Warp grid 2(M) x 4(N), each warp 64x32 = 4x4 m16n8k16 tiles.
// smem pitch 72 halves (144B): bank = (4*lq + lr) % 32 -> conflict-free.
// ===========================================================================
#define GM_BK     64
#define GM_PITCH  72
#define GM_STAGE  (128 * GM_PITCH)                 // halves per stage per operand
#define GM_SMEM_BYTES (4 * GM_STAGE * 2)           // 73728

template <bool HALF_OUT>
static __device__ __forceinline__ void gemm_body(
    const __half* __restrict__ X, const __half* __restrict__ W,
    void* __restrict__ OutV, int N, int K)
{
    extern __shared__ __half smh[];
    __half* As = smh;
    __half* Bs = smh + 2 * GM_STAGE;
    const uint32_t smb = smem_u32(smh);

    const int tid  = threadIdx.x;
    const int wid  = tid >> 5;
    const int lane = tid & 31;
    const int bm   = blockIdx.y * 128;
    const int bn   = blockIdx.x * 128;

    const int wm = (wid & 1) * 64;
    const int wn = (wid >> 1) * 32;

    const int lq = lane >> 2;
    const int lr = lane & 3;

    float d[4][4][4];
#pragma unroll
    for (int mt = 0; mt < 4; mt++)
#pragma unroll
        for (int nt = 0; nt < 4; nt++)
#pragma unroll
            for (int i = 0; i < 4; i++) d[mt][nt][i] = 0.f;

    const int nchunks = K / GM_BK;    // 16

    auto load_stage = [&](int chunk) {
        const int s = chunk & 1;
        const int k0 = chunk * GM_BK;
#pragma unroll
        for (int p = 0; p < 8; p++) {
            int idx = tid + 256 * p;            // 0..2047
            int op  = idx >> 10;                // 0: X, 1: W
            int r   = (idx >> 3) & 127;
            int c   = idx & 7;                  // 16B chunk in 128B row
            const __half* src = (op ? W + (size_t)(bn + r) * K
                                    : X + (size_t)(bm + r) * K) + k0 + c * 8;
            uint32_t dst = smb +
                (uint32_t)((op ? 2 * GM_STAGE : 0) + s * GM_STAGE + r * GM_PITCH) * 2
                + c * 16;
            cp16(dst, src);
        }
        cp_commit();
    };

    load_stage(0);
    load_stage(1);

    for (int j = 0; j < nchunks; j++) {
        if (j + 1 < nchunks) cp_wait1(); else cp_wait0();
        __syncthreads();

        const int s = j & 1;
        const __half* as = As + s * GM_STAGE;
        const __half* bs = Bs + s * GM_STAGE;

#pragma unroll
        for (int kk = 0; kk < 4; kk++) {         // 4 k-steps of 16
            uint32_t af[4][4], bf[4][2];
#pragma unroll
            for (int mt = 0; mt < 4; mt++) {
                const __half* ap = as + (wm + mt * 16 + lq) * GM_PITCH + kk * 16 + 2 * lr;
                af[mt][0] = *(const uint32_t*)(ap);
                af[mt][1] = *(const uint32_t*)(ap + 8 * GM_PITCH);
                af[mt][2] = *(const uint32_t*)(ap + 8);
                af[mt][3] = *(const uint32_t*)(ap + 8 * GM_PITCH + 8);
            }
#pragma unroll
            for (int nt = 0; nt < 4; nt++) {
                const __half* bp = bs + (wn + nt * 8 + lq) * GM_PITCH + kk * 16 + 2 * lr;
                bf[nt][0] = *(const uint32_t*)(bp);
                bf[nt][1] = *(const uint32_t*)(bp + 8);
            }
#pragma unroll
            for (int mt = 0; mt < 4; mt++)
#pragma unroll
                for (int nt = 0; nt < 4; nt++)
                    mma_f16(d[mt][nt], af[mt], bf[nt][0], bf[nt][1]);
        }
        __syncthreads();
        if (j + 2 < nchunks) load_stage(j + 2);
    }

#pragma unroll
    for (int mt = 0; mt < 4; mt++) {
#pragma unroll
        for (int nt = 0; nt < 4; nt++) {
            int r = bm + wm + mt * 16 + lq;
            int c = bn + wn + nt * 8 + 2 * lr;
            if (HALF_OUT) {
                __half* Out = (__half*)OutV;
                __half2 h0 = __floats2half2_rn(d[mt][nt][0], d[mt][nt][1]);
                __half2 h1 = __floats2half2_rn(d[mt][nt][2], d[mt][nt][3]);
                *(uint32_t*)(Out + (size_t)r * N + c)       = h2u(h0);
                *(uint32_t*)(Out + (size_t)(r + 8) * N + c) = h2u(h1);
            } else {
                float* Out = (float*)OutV;
                *(float2*)(Out + (size_t)r * N + c) =
                    make_float2(d[mt][nt][0], d[mt][nt][1]);
                *(float2*)(Out + (size_t)(r + 8) * N + c) =
                    make_float2(d[mt][nt][2], d[mt][nt][3]);
            }
        }
    }
}

__global__ __launch_bounds__(256, 2) void sgemm_qkv(
    const __half* __restrict__ x0, const __half* __restrict__ x1,
    const __half* __restrict__ x2,
    const __half* __restrict__ w0, const __half* __restrict__ w1,
    const __half* __restrict__ w2,
    __half* __restrict__ o0, __half* __restrict__ o1, __half* __restrict__ o2)
{
    const __half* X = (blockIdx.z == 0) ? x0 : (blockIdx.z == 1) ? x1 : x2;
    const __half* W = (blockIdx.z == 0) ? w0 : (blockIdx.z == 1) ? w1 : w2;
    __half*       O = (blockIdx.z == 0) ? o0 : (blockIdx.z == 1) ? o1 : o2;
    gemm_body<true>(X, W, O, Dm, Dm);
}

__global__ __launch_bounds__(256, 2) void sgemm_out(
    const __half* __restrict__ X, const __half* __restrict__ W,
    float* __restrict__ Out)
{
    gemm_body<false>(X, W, Out, Dm, Dm);
}

// ===========================================================================
// mask tile flags: 128q x 64k tiles
// ===========================================================================
__global__ __launch_bounds__(256) void mask_flags(const int* __restrict__ mask)
{
    const int kt = blockIdx.x & 31;
    const int qt = blockIdx.x >> 5;
    const int tid = threadIdx.x;
    int any0 = 0;
#pragma unroll
    for (int p = 0; p < 8; p++) {
        int lin = (tid + 256 * p) * 4;
        int row = lin >> 6;
        int col = lin & 63;
        int4 m = *(const int4*)(mask + (size_t)(qt * 128 + row) * Sq + kt * 64 + col);
        any0 |= (m.x == 0) | (m.y == 0) | (m.z == 0) | (m.w == 0);
    }
    any0 = __syncthreads_or(any0);
    if (tid == 0) g_maskflag[blockIdx.x] = any0;
}

// ===========================================================================
// fp16 tensor-core flash attention, 64-key tiles, P register-resident.
// CTA = (128 q-rows, h, b), 8 warps; warp w owns rows [16w,16w+16).
// ===========================================================================
#define AP 72                                  // pitch (halves) for Q/K/V
#define QSTGH (128 * AP)                       // 9216 halves
#define KSTGH (64 * AP)                        // 4608
#define ATT_Q_OFF 0
#define ATT_K_OFF QSTGH                        // halves
#define ATT_V_OFF (QSTGH + 2 * KSTGH)
#define ATT_SMEM_HALVES (QSTGH + 4 * KSTGH)    // 27648
#define ATT_SMEM_BYTES  (ATT_SMEM_HALVES * 2)  // 55296

__global__ __launch_bounds__(256, 2) void attn_mma(
    const __half* __restrict__ Q, const __half* __restrict__ Kg,
    const __half* __restrict__ Vg, const int* __restrict__ mask,
    __half* __restrict__ Out)
{
    extern __shared__ __half smh[];
    const uint32_t smb = smem_u32(smh);

    const int qt  = blockIdx.x;
    const int qb  = qt * 128;
    const int h   = blockIdx.y;
    const int b   = blockIdx.z;
    const int tid = threadIdx.x;
    const int w   = tid >> 5;
    const int lane = tid & 31;
    const int lq  = lane >> 2;
    const int lr  = lane & 3;

    const size_t base = ((size_t)b * Sq) * Dm + (size_t)h * HDm;

    // 64-key K/V tile -> buffer s
    auto load_kv = [&](int kb, int s) {
#pragma unroll
        for (int p = 0; p < 4; p++) {
            int idx = tid + 256 * p;            // 0..1023
            int op  = idx >> 9;                 // 0: K, 1: V
            int r   = (idx >> 3) & 63;
            int c   = idx & 7;
            const __half* src = (op ? Vg : Kg) + base + (size_t)(kb + r) * Dm + c * 8;
            uint32_t dst = smb +
                (uint32_t)((op ? ATT_V_OFF : ATT_K_OFF) + s * KSTGH + r * AP) * 2
                + c * 16;
            cp16(dst, src);
        }
        cp_commit();
    };

    // prologue: Q tile (128x64) + K/V tile 0
    {
#pragma unroll
        for (int p = 0; p < 4; p++) {
            int idx = tid + 256 * p;            // 0..1023
            int r   = idx >> 3;                 // 0..127
            int c   = idx & 7;
            cp16(smb + (uint32_t)(ATT_Q_OFF + r * AP) * 2 + c * 16,
                 Q + base + (size_t)(qb + r) * Dm + c * 8);
        }
        cp_commit();
        load_kv(0, 0);
        cp_wait0();
        __syncthreads();
    }

    // Q fragments, scale 0.125 folded (pow2 exact in fp16)
    uint32_t qf[4][4];
    {
        const __half2 sc = __float2half2_rn(0.125f);
        const __half* qs = smh + ATT_Q_OFF + (w * 16 + lq) * AP + 2 * lr;
#pragma unroll
        for (int kt = 0; kt < 4; kt++) {
            __half2 q0 = *(const __half2*)(qs + kt * 16);
            __half2 q1 = *(const __half2*)(qs + kt * 16 + 8 * AP);
            __half2 q2 = *(const __half2*)(qs + kt * 16 + 8);
            __half2 q3 = *(const __half2*)(qs + kt * 16 + 8 * AP + 8);
            qf[kt][0] = h2u(__hmul2(q0, sc));
            qf[kt][1] = h2u(__hmul2(q1, sc));
            qf[kt][2] = h2u(__hmul2(q2, sc));
            qf[kt][3] = h2u(__hmul2(q3, sc));
        }
    }

    float o[8][4];
#pragma unroll
    for (int nt = 0; nt < 8; nt++)
        o[nt][0] = o[nt][1] = o[nt][2] = o[nt][3] = 0.f;
    float m0 = -INFINITY, m1 = -INFINITY, l0 = 0.f, l1 = 0.f;

    const int qrow0 = qb + w * 16 + lq;

    for (int kt_i = 0; kt_i < 32; kt_i++) {
        const int kb = kt_i * 64;
        const int s  = kt_i & 1;
        cp_wait0();
        __syncthreads();
        if (kt_i + 1 < 32) load_kv(kb + 64, s ^ 1);

        const __half* ks = smh + ATT_K_OFF + s * KSTGH;

        // ---- S = Q @ K^T : 8 n-tiles of 8 keys
        float d[8][4];
#pragma unroll
        for (int nt = 0; nt < 8; nt++)
            d[nt][0] = d[nt][1] = d[nt][2] = d[nt][3] = 0.f;

#pragma unroll
        for (int kt = 0; kt < 4; kt++) {
#pragma unroll
            for (int nt = 0; nt < 8; nt++) {
                const __half* bp = ks + (nt * 8 + lq) * AP + kt * 16 + 2 * lr;
                uint32_t b0 = *(const uint32_t*)(bp);
                uint32_t b1 = *(const uint32_t*)(bp + 8);
                mma_f16(d[nt], qf[kt], b0, b1);
            }
        }

        if (g_maskflag[qt * 32 + kt_i]) {
            const int* mr0 = mask + (size_t)qrow0 * Sq + kb + 2 * lr;
            const int* mr1 = mr0 + 8 * Sq;
#pragma unroll
            for (int nt = 0; nt < 8; nt++) {
                int2 a = *(const int2*)(mr0 + nt * 8);
                int2 c = *(const int2*)(mr1 + nt * 8);
                if (a.x == 0) d[nt][0] = -1e9f;
                if (a.y == 0) d[nt][1] = -1e9f;
                if (c.x == 0) d[nt][2] = -1e9f;
                if (c.y == 0) d[nt][3] = -1e9f;
            }
        }

        // ---- online softmax (rows lq / lq+8), quad reduction
        float mx0 = -INFINITY, mx1 = -INFINITY;
#pragma unroll
        for (int nt = 0; nt < 8; nt++) {
            mx0 = fmaxf(mx0, fmaxf(d[nt][0], d[nt][1]));
            mx1 = fmaxf(mx1, fmaxf(d[nt][2], d[nt][3]));
        }
        mx0 = fmaxf(mx0, __shfl_xor_sync(0xffffffffu, mx0, 1));
        mx0 = fmaxf(mx0, __shfl_xor_sync(0xffffffffu, mx0, 2));
        mx1 = fmaxf(mx1, __shfl_xor_sync(0xffffffffu, mx1, 1));
        mx1 = fmaxf(mx1, __shfl_xor_sync(0xffffffffu, mx1, 2));

        float mn0 = fmaxf(m0, mx0), mn1 = fmaxf(m1, mx1);
        float al0 = __expf(m0 - mn0), al1 = __expf(m1 - mn1);
        m0 = mn0; m1 = mn1;

        float rs0 = 0.f, rs1 = 0.f;
#pragma unroll
        for (int nt = 0; nt < 8; nt++) {
            d[nt][0] = __expf(d[nt][0] - mn0);
            d[nt][1] = __expf(d[nt][1] - mn0);
            d[nt][2] = __expf(d[nt][2] - mn1);
            d[nt][3] = __expf(d[nt][3] - mn1);
            rs0 += d[nt][0] + d[nt][1];
            rs1 += d[nt][2] + d[nt][3];
        }
        rs0 += __shfl_xor_sync(0xffffffffu, rs0, 1);
        rs0 += __shfl_xor_sync(0xffffffffu, rs0, 2);
        rs1 += __shfl_xor_sync(0xffffffffu, rs1, 1);
        rs1 += __shfl_xor_sync(0xffffffffu, rs1, 2);
        l0 = l0 * al0 + rs0;
        l1 = l1 * al1 + rs1;

#pragma unroll
        for (int nt = 0; nt < 8; nt++) {
            o[nt][0] *= al0; o[nt][1] *= al0;
            o[nt][2] *= al1; o[nt][3] *= al1;
        }

        // ---- P fragments straight from D-fragments (register-resident P)
        uint32_t pa[4][4];
#pragma unroll
        for (int kt = 0; kt < 4; kt++) {
            pa[kt][0] = h2u(__floats2half2_rn(d[2*kt][0],   d[2*kt][1]));
            pa[kt][1] = h2u(__floats2half2_rn(d[2*kt][2],   d[2*kt][3]));
            pa[kt][2] = h2u(__floats2half2_rn(d[2*kt+1][0], d[2*kt+1][1]));
            pa[kt][3] = h2u(__floats2half2_rn(d[2*kt+1][2], d[2*kt+1][3]));
        }

        // ---- O += P @ V : V via ldmatrix.x4.trans (row-major -> B frags)
        const uint32_t vlane = smb + (uint32_t)(ATT_V_OFF + s * KSTGH) * 2
                             + (uint32_t)(lane & 15) * (AP * 2)
                             + ((lane >> 4) ? 16u : 0u);
#pragma unroll
        for (int ntp = 0; ntp < 4; ntp++) {
#pragma unroll
            for (int kt = 0; kt < 4; kt++) {
                uint32_t b0, b1, b2, b3;
                ldsm_x4_t(b0, b1, b2, b3,
                          vlane + (uint32_t)(kt * 16 * AP * 2) + (uint32_t)(ntp * 32));
                mma_f16(o[2*ntp],     pa[kt], b0, b1);
                mma_f16(o[2*ntp + 1], pa[kt], b2, b3);
            }
        }
    }

    // ---- epilogue: divide, store half2
    float inv0 = 1.f / l0, inv1 = 1.f / l1;
    __half* out0 = Out + base + (size_t)qrow0 * Dm + 2 * lr;
    __half* out1 = out0 + (size_t)8 * Dm;
#pragma unroll
    for (int nt = 0; nt < 8; nt++) {
        __half2 h0 = __floats2half2_rn(o[nt][0] * inv0, o[nt][1] * inv0);
        __half2 h1 = __floats2half2_rn(o[nt][2] * inv1, o[nt][3] * inv1);
        *(uint32_t*)(out0 + nt * 8) = h2u(h0);
        *(uint32_t*)(out1 + nt * 8) = h2u(h1);
    }
}

// ===========================================================================
extern "C" void kernel_launch(void* const* d_in, const int* in_sizes, int n_in,
                              void* d_out, int out_size)
{
    (void)in_sizes; (void)n_in; (void)out_size;
    const float* query = (const float*)d_in[0];
    const float* key_  = (const float*)d_in[1];
    const float* value = (const float*)d_in[2];
    const int*   mask  = (const int*)d_in[3];
    const float* w_q   = (const float*)d_in[4];
    const float* w_k   = (const float*)d_in[5];
    const float* w_v   = (const float*)d_in[6];
    const float* w_o   = (const float*)d_in[7];
    float* out = (float*)d_out;

    __half *q, *k, *v, *attn, *xq, *xk, *xv, *wq, *wk, *wv, *wo;
    cudaGetSymbolAddress((void**)&q,    g_q);
    cudaGetSymbolAddress((void**)&k,    g_k);
    cudaGetSymbolAddress((void**)&v,    g_v);
    cudaGetSymbolAddress((void**)&attn, g_attn);
    cudaGetSymbolAddress((void**)&xq,   g_xq);
    cudaGetSymbolAddress((void**)&xk,   g_xk);
    cudaGetSymbolAddress((void**)&xv,   g_xv);
    cudaGetSymbolAddress((void**)&wq,   g_wq);
    cudaGetSymbolAddress((void**)&wk,   g_wk);
    cudaGetSymbolAddress((void**)&wv,   g_wv);
    cudaGetSymbolAddress((void**)&wo,   g_wo);

    cudaFuncSetAttribute(sgemm_qkv,
                         cudaFuncAttributeMaxDynamicSharedMemorySize, GM_SMEM_BYTES);
    cudaFuncSetAttribute(sgemm_out,
                         cudaFuncAttributeMaxDynamicSharedMemorySize, GM_SMEM_BYTES);
    cudaFuncSetAttribute(attn_mma,
                         cudaFuncAttributeMaxDynamicSharedMemorySize, ATT_SMEM_BYTES);

    const int NX4 = (Mrows * Dm) / 4;
    const int NW4 = (Dm * Dm) / 4;
    h_conv3<<<dim3(296, 1, 3), 256>>>(query, key_, value, xq, xk, xv, NX4);
    h_conv4<<<dim3(148, 1, 4), 256>>>(w_q, w_k, w_v, w_o, wq, wk, wv, wo, NW4);
    mask_flags<<<512, 256>>>(mask);

    dim3 gqkv(Dm / 128, Mrows / 128, 3);   // (8, 64, 3)
    sgemm_qkv<<<gqkv, 256, GM_SMEM_BYTES>>>(xq, xk, xv, wq, wk, wv, q, k, v);

    dim3 ga(Sq / 128, Hn, Bsz);            // (16, 16, 4)
    attn_mma<<<ga, 256, ATT_SMEM_BYTES>>>(q, k, v, mask, attn);

    dim3 gg(Dm / 128, Mrows / 128);        // (8, 64)
    sgemm_out<<<gg, 256, GM_SMEM_BYTES>>>(attn, wo, out);
}

// round 8
// speedup vs baseline: 7.0000x; 1.0027x over previous
#include <cuda_runtime.h>
#include <cuda_fp16.h>
#include <math.h>
#include <stdint.h>

#define Bsz 4
#define Sq  2048
#define Dm  1024
#define Hn  16
#define HDm 64
#define Mrows (Bsz * Sq)   // 8192

// Scratch (device globals — no allocation in kernel_launch)
__device__ __half g_q[(size_t)Mrows * Dm];
__device__ __half g_k[(size_t)Mrows * Dm];
__device__ __half g_v[(size_t)Mrows * Dm];
__device__ __half g_attn[(size_t)Mrows * Dm];
__device__ __half g_xq[(size_t)Mrows * Dm];
__device__ __half g_xk[(size_t)Mrows * Dm];
__device__ __half g_xv[(size_t)Mrows * Dm];
__device__ __half g_wq[(size_t)Dm * Dm];
__device__ __half g_wk[(size_t)Dm * Dm];
__device__ __half g_wv[(size_t)Dm * Dm];
__device__ __half g_wo[(size_t)Dm * Dm];
__device__ int    g_maskflag[512];    // [qtile(16)][ktile(32)]

// ===========================================================================
// helpers
// ===========================================================================
static __device__ __forceinline__ uint32_t smem_u32(const void* p) {
    uint32_t a;
    asm("{ .reg .u64 t; cvta.to.shared.u64 t, %1; cvt.u32.u64 %0, t; }"
        : "=r"(a) : "l"(p));
    return a;
}

static __device__ __forceinline__ void cp16(uint32_t dst, const void* src) {
    asm volatile("cp.async.cg.shared.global [%0], [%1], 16;"
                 :: "r"(dst), "l"(src) : "memory");
}
static __device__ __forceinline__ void cp_commit() {
    asm volatile("cp.async.commit_group;" ::: "memory");
}
static __device__ __forceinline__ void cp_wait1() {
    asm volatile("cp.async.wait_group 1;" ::: "memory");
}
static __device__ __forceinline__ void cp_wait0() {
    asm volatile("cp.async.wait_group 0;" ::: "memory");
}

static __device__ __forceinline__ uint32_t h2u(__half2 h) {
    uint32_t u;
    __builtin_memcpy(&u, &h, 4);
    return u;
}

// D(16x8,f32) += A(16x16,f16,row) * B(16x8,f16,col)
static __device__ __forceinline__ void mma_f16(
    float* d, const uint32_t* a, uint32_t b0, uint32_t b1)
{
    asm volatile(
        "mma.sync.aligned.m16n8k16.row.col.f32.f16.f16.f32 "
        "{%0,%1,%2,%3}, {%4,%5,%6,%7}, {%8,%9}, {%0,%1,%2,%3};"
        : "+f"(d[0]), "+f"(d[1]), "+f"(d[2]), "+f"(d[3])
        : "r"(a[0]), "r"(a[1]), "r"(a[2]), "r"(a[3]),
          "r"(b0), "r"(b1));
}

// ldmatrix x4 transposed (for V as PV B-operand)
static __device__ __forceinline__ void ldsm_x4_t(
    uint32_t& b0, uint32_t& b1, uint32_t& b2, uint32_t& b3, uint32_t addr)
{
    asm volatile(
        "ldmatrix.sync.aligned.m8n8.x4.trans.shared.b16 {%0,%1,%2,%3}, [%4];"
        : "=r"(b0), "=r"(b1), "=r"(b2), "=r"(b3) : "r"(addr));
}

// ===========================================================================
// fp32 -> fp16 conversion (merged variants)
// ===========================================================================
__global__ __launch_bounds__(256) void h_conv3(
    const float* __restrict__ s0, const float* __restrict__ s1,
    const float* __restrict__ s2,
    __half* __restrict__ d0, __half* __restrict__ d1, __half* __restrict__ d2,
    int n4)
{
    const float* src = (blockIdx.z == 0) ? s0 : (blockIdx.z == 1) ? s1 : s2;
    __half*      dst = (blockIdx.z == 0) ? d0 : (blockIdx.z == 1) ? d1 : d2;
    int i = blockIdx.x * 256 + threadIdx.x;
    int stride = gridDim.x * 256;
    for (; i < n4; i += stride) {
        float4 v = ((const float4*)src)[i];
        __half2 h0 = __floats2half2_rn(v.x, v.y);
        __half2 h1 = __floats2half2_rn(v.z, v.w);
        uint2 u;
        u.x = h2u(h0); u.y = h2u(h1);
        ((uint2*)dst)[i] = u;
    }
}

__global__ __launch_bounds__(256) void h_conv4(
    const float* __restrict__ s0, const float* __restrict__ s1,
    const float* __restrict__ s2, const float* __restrict__ s3,
    __half* __restrict__ d0, __half* __restrict__ d1,
    __half* __restrict__ d2, __half* __restrict__ d3,
    int n4)
{
    const float* src = (blockIdx.z == 0) ? s0 : (blockIdx.z == 1) ? s1
                     : (blockIdx.z == 2) ? s2 : s3;
    __half*      dst = (blockIdx.z == 0) ? d0 : (blockIdx.z == 1) ? d1
                     : (blockIdx.z == 2) ? d2 : d3;
    int i = blockIdx.x * 256 + threadIdx.x;
    int stride = gridDim.x * 256;
    for (; i < n4; i += stride) {
        float4 v = ((const float4*)src)[i];
        __half2 h0 = __floats2half2_rn(v.x, v.y);
        __half2 h1 = __floats2half2_rn(v.z, v.w);
        uint2 u;
        u.x = h2u(h0); u.y = h2u(h1);
        ((uint2*)dst)[i] = u;
    }
}

// ===========================================================================
// fp16 GEMM: Out[M][N] = X[M][K] @ W[N][K]^T, f32 accum.
// CTA 128x128, BK=64 halves, 2-stage cp.async, 256 threads, occ 2.
// Warp grid 2(M) x 4(N), each warp 64x32 = 4x4 m16n8k16 tiles.
// smem pitch 72 halves (144B): bank = (4*lq + lr) % 32 -> conflict-free.
// ===========================================================================
#define GM_BK     64
#define GM_PITCH  72
#define GM_STAGE  (128 * GM_PITCH)                 // halves per stage per operand
#define GM_SMEM_BYTES (4 * GM_STAGE * 2)           // 73728

template <bool HALF_OUT>
static __device__ __forceinline__ void gemm_body(
    const __half* __restrict__ X, const __half* __restrict__ W,
    void* __restrict__ OutV, int N, int K)
{
    extern __shared__ __half smh[];
    __half* As = smh;
    __half* Bs = smh + 2 * GM_STAGE;
    const uint32_t smb = smem_u32(smh);

    const int tid  = threadIdx.x;
    const int wid  = tid >> 5;
    const int lane = tid & 31;
    const int bm   = blockIdx.y * 128;
    const int bn   = blockIdx.x * 128;

    const int wm = (wid & 1) * 64;
    const int wn = (wid >> 1) * 32;

    const int lq = lane >> 2;
    const int lr = lane & 3;

    float d[4][4][4];
#pragma unroll
    for (int mt = 0; mt < 4; mt++)
#pragma unroll
        for (int nt = 0; nt < 4; nt++)
#pragma unroll
            for (int i = 0; i < 4; i++) d[mt][nt][i] = 0.f;

    const int nchunks = K / GM_BK;    // 16

    auto load_stage = [&](int chunk) {
        const int s = chunk & 1;
        const int k0 = chunk * GM_BK;
#pragma unroll
        for (int p = 0; p < 8; p++) {
            int idx = tid + 256 * p;            // 0..2047
            int op  = idx >> 10;                // 0: X, 1: W
            int r   = (idx >> 3) & 127;
            int c   = idx & 7;                  // 16B chunk in 128B row
            const __half* src = (op ? W + (size_t)(bn + r) * K
                                    : X + (size_t)(bm + r) * K) + k0 + c * 8;
            uint32_t dst = smb +
                (uint32_t)((op ? 2 * GM_STAGE : 0) + s * GM_STAGE + r * GM_PITCH) * 2
                + c * 16;
            cp16(dst, src);
        }
        cp_commit();
    };

    load_stage(0);
    load_stage(1);

    for (int j = 0; j < nchunks; j++) {
        if (j + 1 < nchunks) cp_wait1(); else cp_wait0();
        __syncthreads();

        const int s = j & 1;
        const __half* as = As + s * GM_STAGE;
        const __half* bs = Bs + s * GM_STAGE;

#pragma unroll
        for (int kk = 0; kk < 4; kk++) {         // 4 k-steps of 16
            uint32_t af[4][4], bf[4][2];
#pragma unroll
            for (int mt = 0; mt < 4; mt++) {
                const __half* ap = as + (wm + mt * 16 + lq) * GM_PITCH + kk * 16 + 2 * lr;
                af[mt][0] = *(const uint32_t*)(ap);
                af[mt][1] = *(const uint32_t*)(ap + 8 * GM_PITCH);
                af[mt][2] = *(const uint32_t*)(ap + 8);
                af[mt][3] = *(const uint32_t*)(ap + 8 * GM_PITCH + 8);
            }
#pragma unroll
            for (int nt = 0; nt < 4; nt++) {
                const __half* bp = bs + (wn + nt * 8 + lq) * GM_PITCH + kk * 16 + 2 * lr;
                bf[nt][0] = *(const uint32_t*)(bp);
                bf[nt][1] = *(const uint32_t*)(bp + 8);
            }
#pragma unroll
            for (int mt = 0; mt < 4; mt++)
#pragma unroll
                for (int nt = 0; nt < 4; nt++)
                    mma_f16(d[mt][nt], af[mt], bf[nt][0], bf[nt][1]);
        }
        __syncthreads();
        if (j + 2 < nchunks) load_stage(j + 2);
    }

#pragma unroll
    for (int mt = 0; mt < 4; mt++) {
#pragma unroll
        for (int nt = 0; nt < 4; nt++) {
            int r = bm + wm + mt * 16 + lq;
            int c = bn + wn + nt * 8 + 2 * lr;
            if (HALF_OUT) {
                __half* Out = (__half*)OutV;
                __half2 h0 = __floats2half2_rn(d[mt][nt][0], d[mt][nt][1]);
                __half2 h1 = __floats2half2_rn(d[mt][nt][2], d[mt][nt][3]);
                *(uint32_t*)(Out + (size_t)r * N + c)       = h2u(h0);
                *(uint32_t*)(Out + (size_t)(r + 8) * N + c) = h2u(h1);
            } else {
                float* Out = (float*)OutV;
                *(float2*)(Out + (size_t)r * N + c) =
                    make_float2(d[mt][nt][0], d[mt][nt][1]);
                *(float2*)(Out + (size_t)(r + 8) * N + c) =
                    make_float2(d[mt][nt][2], d[mt][nt][3]);
            }
        }
    }
}

__global__ __launch_bounds__(256, 2) void sgemm_qkv(
    const __half* __restrict__ x0, const __half* __restrict__ x1,
    const __half* __restrict__ x2,
    const __half* __restrict__ w0, const __half* __restrict__ w1,
    const __half* __restrict__ w2,
    __half* __restrict__ o0, __half* __restrict__ o1, __half* __restrict__ o2)
{
    const __half* X = (blockIdx.z == 0) ? x0 : (blockIdx.z == 1) ? x1 : x2;
    const __half* W = (blockIdx.z == 0) ? w0 : (blockIdx.z == 1) ? w1 : w2;
    __half*       O = (blockIdx.z == 0) ? o0 : (blockIdx.z == 1) ? o1 : o2;
    gemm_body<true>(X, W, O, Dm, Dm);
}

__global__ __launch_bounds__(256, 2) void sgemm_out(
    const __half* __restrict__ X, const __half* __restrict__ W,
    float* __restrict__ Out)
{
    gemm_body<false>(X, W, Out, Dm, Dm);
}

// ===========================================================================
// mask tile flags: 128q x 64k tiles
// ===========================================================================
__global__ __launch_bounds__(256) void mask_flags(const int* __restrict__ mask)
{
    const int kt = blockIdx.x & 31;
    const int qt = blockIdx.x >> 5;
    const int tid = threadIdx.x;
    int any0 = 0;
#pragma unroll
    for (int p = 0; p < 8; p++) {
        int lin = (tid + 256 * p) * 4;
        int row = lin >> 6;
        int col = lin & 63;
        int4 m = *(const int4*)(mask + (size_t)(qt * 128 + row) * Sq + kt * 64 + col);
        any0 |= (m.x == 0) | (m.y == 0) | (m.z == 0) | (m.w == 0);
    }
    any0 = __syncthreads_or(any0);
    if (tid == 0) g_maskflag[blockIdx.x] = any0;
}

// ===========================================================================
// fp16 tensor-core flash attention, 64-key tiles, P register-resident.
// CTA = (128 q-rows, h, b), 8 warps; warp w owns rows [16w,16w+16).
// ===========================================================================
#define AP 72                                  // pitch (halves) for Q/K/V
#define QSTGH (128 * AP)                       // 9216 halves
#define KSTGH (64 * AP)                        // 4608
#define ATT_Q_OFF 0
#define ATT_K_OFF QSTGH                        // halves
#define ATT_V_OFF (QSTGH + 2 * KSTGH)
#define ATT_SMEM_HALVES (QSTGH + 4 * KSTGH)    // 27648
#define ATT_SMEM_BYTES  (ATT_SMEM_HALVES * 2)  // 55296

__global__ __launch_bounds__(256, 2) void attn_mma(
    const __half* __restrict__ Q, const __half* __restrict__ Kg,
    const __half* __restrict__ Vg, const int* __restrict__ mask,
    __half* __restrict__ Out)
{
    extern __shared__ __half smh[];
    const uint32_t smb = smem_u32(smh);

    const int qt  = blockIdx.x;
    const int qb  = qt * 128;
    const int h   = blockIdx.y;
    const int b   = blockIdx.z;
    const int tid = threadIdx.x;
    const int w   = tid >> 5;
    const int lane = tid & 31;
    const int lq  = lane >> 2;
    const int lr  = lane & 3;

    const size_t base = ((size_t)b * Sq) * Dm + (size_t)h * HDm;

    // 64-key K/V tile -> buffer s
    auto load_kv = [&](int kb, int s) {
#pragma unroll
        for (int p = 0; p < 4; p++) {
            int idx = tid + 256 * p;            // 0..1023
            int op  = idx >> 9;                 // 0: K, 1: V
            int r   = (idx >> 3) & 63;
            int c   = idx & 7;
            const __half* src = (op ? Vg : Kg) + base + (size_t)(kb + r) * Dm + c * 8;
            uint32_t dst = smb +
                (uint32_t)((op ? ATT_V_OFF : ATT_K_OFF) + s * KSTGH + r * AP) * 2
                + c * 16;
            cp16(dst, src);
        }
        cp_commit();
    };

    // prologue: Q tile (128x64) + K/V tile 0
    {
#pragma unroll
        for (int p = 0; p < 4; p++) {
            int idx = tid + 256 * p;            // 0..1023
            int r   = idx >> 3;                 // 0..127
            int c   = idx & 7;
            cp16(smb + (uint32_t)(ATT_Q_OFF + r * AP) * 2 + c * 16,
                 Q + base + (size_t)(qb + r) * Dm + c * 8);
        }
        cp_commit();
        load_kv(0, 0);
        cp_wait0();
        __syncthreads();
    }

    // Q fragments, scale 0.125 folded (pow2 exact in fp16)
    uint32_t qf[4][4];
    {
        const __half2 sc = __float2half2_rn(0.125f);
        const __half* qs = smh + ATT_Q_OFF + (w * 16 + lq) * AP + 2 * lr;
#pragma unroll
        for (int kt = 0; kt < 4; kt++) {
            __half2 q0 = *(const __half2*)(qs + kt * 16);
            __half2 q1 = *(const __half2*)(qs + kt * 16 + 8 * AP);
            __half2 q2 = *(const __half2*)(qs + kt * 16 + 8);
            __half2 q3 = *(const __half2*)(qs + kt * 16 + 8 * AP + 8);
            qf[kt][0] = h2u(__hmul2(q0, sc));
            qf[kt][1] = h2u(__hmul2(q1, sc));
            qf[kt][2] = h2u(__hmul2(q2, sc));
            qf[kt][3] = h2u(__hmul2(q3, sc));
        }
    }

    float o[8][4];
#pragma unroll
    for (int nt = 0; nt < 8; nt++)
        o[nt][0] = o[nt][1] = o[nt][2] = o[nt][3] = 0.f;
    float m0 = -INFINITY, m1 = -INFINITY, l0 = 0.f, l1 = 0.f;

    const int qrow0 = qb + w * 16 + lq;

    for (int kt_i = 0; kt_i < 32; kt_i++) {
        const int kb = kt_i * 64;
        const int s  = kt_i & 1;
        cp_wait0();
        __syncthreads();
        if (kt_i + 1 < 32) load_kv(kb + 64, s ^ 1);

        const __half* ks = smh + ATT_K_OFF + s * KSTGH;

        // ---- S = Q @ K^T : 8 n-tiles of 8 keys
        float d[8][4];
#pragma unroll
        for (int nt = 0; nt < 8; nt++)
            d[nt][0] = d[nt][1] = d[nt][2] = d[nt][3] = 0.f;

#pragma unroll
        for (int kt = 0; kt < 4; kt++) {
#pragma unroll
            for (int nt = 0; nt < 8; nt++) {
                const __half* bp = ks + (nt * 8 + lq) * AP + kt * 16 + 2 * lr;
                uint32_t b0 = *(const uint32_t*)(bp);
                uint32_t b1 = *(const uint32_t*)(bp + 8);
                mma_f16(d[nt], qf[kt], b0, b1);
            }
        }

        if (g_maskflag[qt * 32 + kt_i]) {
            const int* mr0 = mask + (size_t)qrow0 * Sq + kb + 2 * lr;
            const int* mr1 = mr0 + 8 * Sq;
#pragma unroll
            for (int nt = 0; nt < 8; nt++) {
                int2 a = *(const int2*)(mr0 + nt * 8);
                int2 c = *(const int2*)(mr1 + nt * 8);
                if (a.x == 0) d[nt][0] = -1e9f;
                if (a.y == 0) d[nt][1] = -1e9f;
                if (c.x == 0) d[nt][2] = -1e9f;
                if (c.y == 0) d[nt][3] = -1e9f;
            }
        }

        // ---- online softmax (rows lq / lq+8), quad reduction
        float mx0 = -INFINITY, mx1 = -INFINITY;
#pragma unroll
        for (int nt = 0; nt < 8; nt++) {
            mx0 = fmaxf(mx0, fmaxf(d[nt][0], d[nt][1]));
            mx1 = fmaxf(mx1, fmaxf(d[nt][2], d[nt][3]));
        }
        mx0 = fmaxf(mx0, __shfl_xor_sync(0xffffffffu, mx0, 1));
        mx0 = fmaxf(mx0, __shfl_xor_sync(0xffffffffu, mx0, 2));
        mx1 = fmaxf(mx1, __shfl_xor_sync(0xffffffffu, mx1, 1));
        mx1 = fmaxf(mx1, __shfl_xor_sync(0xffffffffu, mx1, 2));

        float mn0 = fmaxf(m0, mx0), mn1 = fmaxf(m1, mx1);
        float al0 = __expf(m0 - mn0), al1 = __expf(m1 - mn1);
        m0 = mn0; m1 = mn1;

        float rs0 = 0.f, rs1 = 0.f;
#pragma unroll
        for (int nt = 0; nt < 8; nt++) {
            d[nt][0] = __expf(d[nt][0] - mn0);
            d[nt][1] = __expf(d[nt][1] - mn0);
            d[nt][2] = __expf(d[nt][2] - mn1);
            d[nt][3] = __expf(d[nt][3] - mn1);
            rs0 += d[nt][0] + d[nt][1];
            rs1 += d[nt][2] + d[nt][3];
        }
        rs0 += __shfl_xor_sync(0xffffffffu, rs0, 1);
        rs0 += __shfl_xor_sync(0xffffffffu, rs0, 2);
        rs1 += __shfl_xor_sync(0xffffffffu, rs1, 1);
        rs1 += __shfl_xor_sync(0xffffffffu, rs1, 2);
        l0 = l0 * al0 + rs0;
        l1 = l1 * al1 + rs1;

#pragma unroll
        for (int nt = 0; nt < 8; nt++) {
            o[nt][0] *= al0; o[nt][1] *= al0;
            o[nt][2] *= al1; o[nt][3] *= al1;
        }

        // ---- P fragments straight from D-fragments (register-resident P)
        uint32_t pa[4][4];
#pragma unroll
        for (int kt = 0; kt < 4; kt++) {
            pa[kt][0] = h2u(__floats2half2_rn(d[2*kt][0],   d[2*kt][1]));
            pa[kt][1] = h2u(__floats2half2_rn(d[2*kt][2],   d[2*kt][3]));
            pa[kt][2] = h2u(__floats2half2_rn(d[2*kt+1][0], d[2*kt+1][1]));
            pa[kt][3] = h2u(__floats2half2_rn(d[2*kt+1][2], d[2*kt+1][3]));
        }

        // ---- O += P @ V : V via ldmatrix.x4.trans (row-major -> B frags)
        const uint32_t vlane = smb + (uint32_t)(ATT_V_OFF + s * KSTGH) * 2
                             + (uint32_t)(lane & 15) * (AP * 2)
                             + ((lane >> 4) ? 16u : 0u);
#pragma unroll
        for (int ntp = 0; ntp < 4; ntp++) {
#pragma unroll
            for (int kt = 0; kt < 4; kt++) {
                uint32_t b0, b1, b2, b3;
                ldsm_x4_t(b0, b1, b2, b3,
                          vlane + (uint32_t)(kt * 16 * AP * 2) + (uint32_t)(ntp * 32));
                mma_f16(o[2*ntp],     pa[kt], b0, b1);
                mma_f16(o[2*ntp + 1], pa[kt], b2, b3);
            }
        }
    }

    // ---- epilogue: divide, store half2
    float inv0 = 1.f / l0, inv1 = 1.f / l1;
    __half* out0 = Out + base + (size_t)qrow0 * Dm + 2 * lr;
    __half* out1 = out0 + (size_t)8 * Dm;
#pragma unroll
    for (int nt = 0; nt < 8; nt++) {
        __half2 h0 = __floats2half2_rn(o[nt][0] * inv0, o[nt][1] * inv0);
        __half2 h1 = __floats2half2_rn(o[nt][2] * inv1, o[nt][3] * inv1);
        *(uint32_t*)(out0 + nt * 8) = h2u(h0);
        *(uint32_t*)(out1 + nt * 8) = h2u(h1);
    }
}

// ===========================================================================
extern "C" void kernel_launch(void* const* d_in, const int* in_sizes, int n_in,
                              void* d_out, int out_size)
{
    (void)in_sizes; (void)n_in; (void)out_size;
    const float* query = (const float*)d_in[0];
    const float* key_  = (const float*)d_in[1];
    const float* value = (const float*)d_in[2];
    const int*   mask  = (const int*)d_in[3];
    const float* w_q   = (const float*)d_in[4];
    const float* w_k   = (const float*)d_in[5];
    const float* w_v   = (const float*)d_in[6];
    const float* w_o   = (const float*)d_in[7];
    float* out = (float*)d_out;

    __half *q, *k, *v, *attn, *xq, *xk, *xv, *wq, *wk, *wv, *wo;
    cudaGetSymbolAddress((void**)&q,    g_q);
    cudaGetSymbolAddress((void**)&k,    g_k);
    cudaGetSymbolAddress((void**)&v,    g_v);
    cudaGetSymbolAddress((void**)&attn, g_attn);
    cudaGetSymbolAddress((void**)&xq,   g_xq);
    cudaGetSymbolAddress((void**)&xk,   g_xk);
    cudaGetSymbolAddress((void**)&xv,   g_xv);
    cudaGetSymbolAddress((void**)&wq,   g_wq);
    cudaGetSymbolAddress((void**)&wk,   g_wk);
    cudaGetSymbolAddress((void**)&wv,   g_wv);
    cudaGetSymbolAddress((void**)&wo,   g_wo);

    cudaFuncSetAttribute(sgemm_qkv,
                         cudaFuncAttributeMaxDynamicSharedMemorySize, GM_SMEM_BYTES);
    cudaFuncSetAttribute(sgemm_out,
                         cudaFuncAttributeMaxDynamicSharedMemorySize, GM_SMEM_BYTES);
    cudaFuncSetAttribute(attn_mma,
                         cudaFuncAttributeMaxDynamicSharedMemorySize, ATT_SMEM_BYTES);

    const int NX4 = (Mrows * Dm) / 4;
    const int NW4 = (Dm * Dm) / 4;
    h_conv3<<<dim3(296, 1, 3), 256>>>(query, key_, value, xq, xk, xv, NX4);
    h_conv4<<<dim3(148, 1, 4), 256>>>(w_q, w_k, w_v, w_o, wq, wk, wv, wo, NW4);
    mask_flags<<<512, 256>>>(mask);

    dim3 gqkv(Dm / 128, Mrows / 128, 3);   // (8, 64, 3)
    sgemm_qkv<<<gqkv, 256, GM_SMEM_BYTES>>>(xq, xk, xv, wq, wk, wv, q, k, v);

    dim3 ga(Sq / 128, Hn, Bsz);            // (16, 16, 4)
    attn_mma<<<ga, 256, ATT_SMEM_BYTES>>>(q, k, v, mask, attn);

    dim3 gg(Dm / 128, Mrows / 128);        // (8, 64)
    sgemm_out<<<gg, 256, GM_SMEM_BYTES>>>(attn, wo, out);
}

// round 9
// speedup vs baseline: 7.4374x; 1.0625x over previous
#include <cuda_runtime.h>
#include <cuda_fp16.h>
#include <math.h>
#include <stdint.h>

#define Bsz 4
#define Sq  2048
#define Dm  1024
#define Hn  16
#define HDm 64
#define Mrows (Bsz * Sq)   // 8192

// Scratch (device globals — no allocation in kernel_launch)
__device__ __half g_q[(size_t)Mrows * Dm];
__device__ __half g_k[(size_t)Mrows * Dm];
__device__ __half g_v[(size_t)Mrows * Dm];
__device__ __half g_attn[(size_t)Mrows * Dm];
__device__ __half g_xq[(size_t)Mrows * Dm];
__device__ __half g_xk[(size_t)Mrows * Dm];
__device__ __half g_xv[(size_t)Mrows * Dm];
__device__ __half g_wq[(size_t)Dm * Dm];
__device__ __half g_wk[(size_t)Dm * Dm];
__device__ __half g_wv[(size_t)Dm * Dm];
__device__ __half g_wo[(size_t)Dm * Dm];
__device__ int    g_maskflag[512];    // [qtile(16)][ktile(32)]

// ===========================================================================
// helpers
// ===========================================================================
static __device__ __forceinline__ uint32_t smem_u32(const void* p) {
    uint32_t a;
    asm("{ .reg .u64 t; cvta.to.shared.u64 t, %1; cvt.u32.u64 %0, t; }"
        : "=r"(a) : "l"(p));
    return a;
}

static __device__ __forceinline__ void cp16(uint32_t dst, const void* src) {
    asm volatile("cp.async.cg.shared.global [%0], [%1], 16;"
                 :: "r"(dst), "l"(src) : "memory");
}
static __device__ __forceinline__ void cp_commit() {
    asm volatile("cp.async.commit_group;" ::: "memory");
}
static __device__ __forceinline__ void cp_wait1() {
    asm volatile("cp.async.wait_group 1;" ::: "memory");
}
static __device__ __forceinline__ void cp_wait0() {
    asm volatile("cp.async.wait_group 0;" ::: "memory");
}

static __device__ __forceinline__ uint32_t h2u(__half2 h) {
    uint32_t u;
    __builtin_memcpy(&u, &h, 4);
    return u;
}

// D(16x8,f32) += A(16x16,f16,row) * B(16x8,f16,col)
static __device__ __forceinline__ void mma_f16(
    float* d, const uint32_t* a, uint32_t b0, uint32_t b1)
{
    asm volatile(
        "mma.sync.aligned.m16n8k16.row.col.f32.f16.f16.f32 "
        "{%0,%1,%2,%3}, {%4,%5,%6,%7}, {%8,%9}, {%0,%1,%2,%3};"
        : "+f"(d[0]), "+f"(d[1]), "+f"(d[2]), "+f"(d[3])
        : "r"(a[0]), "r"(a[1]), "r"(a[2]), "r"(a[3]),
          "r"(b0), "r"(b1));
}

// ldmatrix variants
static __device__ __forceinline__ void ldsm_x4(
    uint32_t& r0, uint32_t& r1, uint32_t& r2, uint32_t& r3, uint32_t addr)
{
    asm volatile(
        "ldmatrix.sync.aligned.m8n8.x4.shared.b16 {%0,%1,%2,%3}, [%4];"
        : "=r"(r0), "=r"(r1), "=r"(r2), "=r"(r3) : "r"(addr));
}
static __device__ __forceinline__ void ldsm_x2(
    uint32_t& r0, uint32_t& r1, uint32_t addr)
{
    asm volatile(
        "ldmatrix.sync.aligned.m8n8.x2.shared.b16 {%0,%1}, [%2];"
        : "=r"(r0), "=r"(r1) : "r"(addr));
}
static __device__ __forceinline__ void ldsm_x4_t(
    uint32_t& b0, uint32_t& b1, uint32_t& b2, uint32_t& b3, uint32_t addr)
{
    asm volatile(
        "ldmatrix.sync.aligned.m8n8.x4.trans.shared.b16 {%0,%1,%2,%3}, [%4];"
        : "=r"(b0), "=r"(b1), "=r"(b2), "=r"(b3) : "r"(addr));
}

// ===========================================================================
// fp32 -> fp16 conversion (merged variants)
// ===========================================================================
__global__ __launch_bounds__(256) void h_conv3(
    const float* __restrict__ s0, const float* __restrict__ s1,
    const float* __restrict__ s2,
    __half* __restrict__ d0, __half* __restrict__ d1, __half* __restrict__ d2,
    int n4)
{
    const float* src = (blockIdx.z == 0) ? s0 : (blockIdx.z == 1) ? s1 : s2;
    __half*      dst = (blockIdx.z == 0) ? d0 : (blockIdx.z == 1) ? d1 : d2;
    int i = blockIdx.x * 256 + threadIdx.x;
    int stride = gridDim.x * 256;
    for (; i < n4; i += stride) {
        float4 v = ((const float4*)src)[i];
        __half2 h0 = __floats2half2_rn(v.x, v.y);
        __half2 h1 = __floats2half2_rn(v.z, v.w);
        uint2 u;
        u.x = h2u(h0); u.y = h2u(h1);
        ((uint2*)dst)[i] = u;
    }
}

__global__ __launch_bounds__(256) void h_conv4(
    const float* __restrict__ s0, const float* __restrict__ s1,
    const float* __restrict__ s2, const float* __restrict__ s3,
    __half* __restrict__ d0, __half* __restrict__ d1,
    __half* __restrict__ d2, __half* __restrict__ d3,
    int n4)
{
    const float* src = (blockIdx.z == 0) ? s0 : (blockIdx.z == 1) ? s1
                     : (blockIdx.z == 2) ? s2 : s3;
    __half*      dst = (blockIdx.z == 0) ? d0 : (blockIdx.z == 1) ? d1
                     : (blockIdx.z == 2) ? d2 : d3;
    int i = blockIdx.x * 256 + threadIdx.x;
    int stride = gridDim.x * 256;
    for (; i < n4; i += stride) {
        float4 v = ((const float4*)src)[i];
        __half2 h0 = __floats2half2_rn(v.x, v.y);
        __half2 h1 = __floats2half2_rn(v.z, v.w);
        uint2 u;
        u.x = h2u(h0); u.y = h2u(h1);
        ((uint2*)dst)[i] = u;
    }
}

// ===========================================================================
// fp16 GEMM: Out[M][N] = X[M][K] @ W[N][K]^T, f32 accum, ldmatrix frags.
// CTA 128x128, BK=64, 2-stage cp.async, 256 threads, occ 2.
// pitch 72 halves (144B): ldmatrix rows land on disjoint bank quads.
// ===========================================================================
#define GM_BK     64
#define GM_PITCH  72
#define GM_STAGE  (128 * GM_PITCH)                 // halves per stage per operand
#define GM_SMEM_BYTES (4 * GM_STAGE * 2)           // 73728

template <bool HALF_OUT>
static __device__ __forceinline__ void gemm_body(
    const __half* __restrict__ X, const __half* __restrict__ W,
    void* __restrict__ OutV, int N, int K)
{
    extern __shared__ __half smh[];
    const uint32_t smb = smem_u32(smh);

    const int tid  = threadIdx.x;
    const int wid  = tid >> 5;
    const int lane = tid & 31;
    const int bm   = blockIdx.y * 128;
    const int bn   = blockIdx.x * 128;

    const int wm = (wid & 1) * 64;
    const int wn = (wid >> 1) * 32;

    const int lq = lane >> 2;
    const int lr = lane & 3;

    // ldmatrix lane-address components (bytes)
    const uint32_t a_row = (uint32_t)(wm + (lane & 15)) * (GM_PITCH * 2)
                         + (uint32_t)(lane >> 4) * 16;
    const uint32_t b_row = (uint32_t)(2 * GM_STAGE * 2)
                         + (uint32_t)(wn + (lane & 7)) * (GM_PITCH * 2)
                         + (uint32_t)((lane >> 3) & 1) * 16;

    float d[4][4][4];
#pragma unroll
    for (int mt = 0; mt < 4; mt++)
#pragma unroll
        for (int nt = 0; nt < 4; nt++)
#pragma unroll
            for (int i = 0; i < 4; i++) d[mt][nt][i] = 0.f;

    const int nchunks = K / GM_BK;    // 16

    auto load_stage = [&](int chunk) {
        const int s = chunk & 1;
        const int k0 = chunk * GM_BK;
#pragma unroll
        for (int p = 0; p < 8; p++) {
            int idx = tid + 256 * p;            // 0..2047
            int op  = idx >> 10;                // 0: X, 1: W
            int r   = (idx >> 3) & 127;
            int c   = idx & 7;                  // 16B chunk in 128B row
            const __half* src = (op ? W + (size_t)(bn + r) * K
                                    : X + (size_t)(bm + r) * K) + k0 + c * 8;
            uint32_t dst = smb +
                (uint32_t)((op ? 2 * GM_STAGE : 0) + s * GM_STAGE + r * GM_PITCH) * 2
                + c * 16;
            cp16(dst, src);
        }
        cp_commit();
    };

    load_stage(0);
    load_stage(1);

    for (int j = 0; j < nchunks; j++) {
        if (j + 1 < nchunks) cp_wait1(); else cp_wait0();
        __syncthreads();

        const int s = j & 1;
        const uint32_t abase = smb + (uint32_t)(s * GM_STAGE) * 2 + a_row;
        const uint32_t bbase = smb + (uint32_t)(s * GM_STAGE) * 2 + b_row;

#pragma unroll
        for (int kk = 0; kk < 4; kk++) {         // 4 k-steps of 16
            uint32_t af[4][4], bf[4][2];
#pragma unroll
            for (int mt = 0; mt < 4; mt++)
                ldsm_x4(af[mt][0], af[mt][1], af[mt][2], af[mt][3],
                        abase + (uint32_t)(mt * 16 * GM_PITCH * 2) + (uint32_t)(kk * 32));
#pragma unroll
            for (int nt = 0; nt < 4; nt++)
                ldsm_x2(bf[nt][0], bf[nt][1],
                        bbase + (uint32_t)(nt * 8 * GM_PITCH * 2) + (uint32_t)(kk * 32));
#pragma unroll
            for (int mt = 0; mt < 4; mt++)
#pragma unroll
                for (int nt = 0; nt < 4; nt++)
                    mma_f16(d[mt][nt], af[mt], bf[nt][0], bf[nt][1]);
        }
        __syncthreads();
        if (j + 2 < nchunks) load_stage(j + 2);
    }

#pragma unroll
    for (int mt = 0; mt < 4; mt++) {
#pragma unroll
        for (int nt = 0; nt < 4; nt++) {
            int r = bm + wm + mt * 16 + lq;
            int c = bn + wn + nt * 8 + 2 * lr;
            if (HALF_OUT) {
                __half* Out = (__half*)OutV;
                __half2 h0 = __floats2half2_rn(d[mt][nt][0], d[mt][nt][1]);
                __half2 h1 = __floats2half2_rn(d[mt][nt][2], d[mt][nt][3]);
                *(uint32_t*)(Out + (size_t)r * N + c)       = h2u(h0);
                *(uint32_t*)(Out + (size_t)(r + 8) * N + c) = h2u(h1);
            } else {
                float* Out = (float*)OutV;
                *(float2*)(Out + (size_t)r * N + c) =
                    make_float2(d[mt][nt][0], d[mt][nt][1]);
                *(float2*)(Out + (size_t)(r + 8) * N + c) =
                    make_float2(d[mt][nt][2], d[mt][nt][3]);
            }
        }
    }
}

__global__ __launch_bounds__(256, 2) void sgemm_qkv(
    const __half* __restrict__ x0, const __half* __restrict__ x1,
    const __half* __restrict__ x2,
    const __half* __restrict__ w0, const __half* __restrict__ w1,
    const __half* __restrict__ w2,
    __half* __restrict__ o0, __half* __restrict__ o1, __half* __restrict__ o2)
{
    const __half* X = (blockIdx.z == 0) ? x0 : (blockIdx.z == 1) ? x1 : x2;
    const __half* W = (blockIdx.z == 0) ? w0 : (blockIdx.z == 1) ? w1 : w2;
    __half*       O = (blockIdx.z == 0) ? o0 : (blockIdx.z == 1) ? o1 : o2;
    gemm_body<true>(X, W, O, Dm, Dm);
}

__global__ __launch_bounds__(256, 2) void sgemm_out(
    const __half* __restrict__ X, const __half* __restrict__ W,
    float* __restrict__ Out)
{
    gemm_body<false>(X, W, Out, Dm, Dm);
}

// ===========================================================================
// mask tile flags: 128q x 64k tiles
// ===========================================================================
__global__ __launch_bounds__(256) void mask_flags(const int* __restrict__ mask)
{
    const int kt = blockIdx.x & 31;
    const int qt = blockIdx.x >> 5;
    const int tid = threadIdx.x;
    int any0 = 0;
#pragma unroll
    for (int p = 0; p < 8; p++) {
        int lin = (tid + 256 * p) * 4;
        int row = lin >> 6;
        int col = lin & 63;
        int4 m = *(const int4*)(mask + (size_t)(qt * 128 + row) * Sq + kt * 64 + col);
        any0 |= (m.x == 0) | (m.y == 0) | (m.z == 0) | (m.w == 0);
    }
    any0 = __syncthreads_or(any0);
    if (tid == 0) g_maskflag[blockIdx.x] = any0;
}

// ===========================================================================
// fp16 tensor-core flash attention, 64-key tiles, P register-resident,
// ldmatrix for K and V fragments.
// ===========================================================================
#define AP 72                                  // pitch (halves) for Q/K/V
#define QSTGH (128 * AP)                       // 9216 halves
#define KSTGH (64 * AP)                        // 4608
#define ATT_Q_OFF 0
#define ATT_K_OFF QSTGH
#define ATT_V_OFF (QSTGH + 2 * KSTGH)
#define ATT_SMEM_HALVES (QSTGH + 4 * KSTGH)    // 27648
#define ATT_SMEM_BYTES  (ATT_SMEM_HALVES * 2)  // 55296

__global__ __launch_bounds__(256, 2) void attn_mma(
    const __half* __restrict__ Q, const __half* __restrict__ Kg,
    const __half* __restrict__ Vg, const int* __restrict__ mask,
    __half* __restrict__ Out)
{
    extern __shared__ __half smh[];
    const uint32_t smb = smem_u32(smh);

    const int qt  = blockIdx.x;
    const int qb  = qt * 128;
    const int h   = blockIdx.y;
    const int b   = blockIdx.z;
    const int tid = threadIdx.x;
    const int w   = tid >> 5;
    const int lane = tid & 31;
    const int lq  = lane >> 2;
    const int lr  = lane & 3;

    const size_t base = ((size_t)b * Sq) * Dm + (size_t)h * HDm;

    auto load_kv = [&](int kb, int s) {
#pragma unroll
        for (int p = 0; p < 4; p++) {
            int idx = tid + 256 * p;            // 0..1023
            int op  = idx >> 9;                 // 0: K, 1: V
            int r   = (idx >> 3) & 63;
            int c   = idx & 7;
            const __half* src = (op ? Vg : Kg) + base + (size_t)(kb + r) * Dm + c * 8;
            uint32_t dst = smb +
                (uint32_t)((op ? ATT_V_OFF : ATT_K_OFF) + s * KSTGH + r * AP) * 2
                + c * 16;
            cp16(dst, src);
        }
        cp_commit();
    };

    // prologue: Q tile + K/V tile 0
    {
#pragma unroll
        for (int p = 0; p < 4; p++) {
            int idx = tid + 256 * p;
            int r   = idx >> 3;
            int c   = idx & 7;
            cp16(smb + (uint32_t)(ATT_Q_OFF + r * AP) * 2 + c * 16,
                 Q + base + (size_t)(qb + r) * Dm + c * 8);
        }
        cp_commit();
        load_kv(0, 0);
        cp_wait0();
        __syncthreads();
    }

    // Q fragments, scale 0.125 folded (pow2 exact in fp16)
    uint32_t qf[4][4];
    {
        const __half2 sc = __float2half2_rn(0.125f);
        const __half* qs = smh + ATT_Q_OFF + (w * 16 + lq) * AP + 2 * lr;
#pragma unroll
        for (int kt = 0; kt < 4; kt++) {
            __half2 q0 = *(const __half2*)(qs + kt * 16);
            __half2 q1 = *(const __half2*)(qs + kt * 16 + 8 * AP);
            __half2 q2 = *(const __half2*)(qs + kt * 16 + 8);
            __half2 q3 = *(const __half2*)(qs + kt * 16 + 8 * AP + 8);
            qf[kt][0] = h2u(__hmul2(q0, sc));
            qf[kt][1] = h2u(__hmul2(q1, sc));
            qf[kt][2] = h2u(__hmul2(q2, sc));
            qf[kt][3] = h2u(__hmul2(q3, sc));
        }
    }

    // K ldmatrix lane address: two n-tiles per x4
    // lanes 0-7: rows ntp*16+(lane&7), k seg 0 | lanes 8-15: same rows, k+8
    // lanes 16-23: rows ntp*16+8+(lane&7)      | lanes 24-31: k+8
    const uint32_t k_lrow = (uint32_t)((lane & 7) + 8 * ((lane >> 4) & 1)) * (AP * 2)
                          + (uint32_t)((lane >> 3) & 1) * 16;
    // V ldmatrix (trans) lane address
    const uint32_t v_lrow = (uint32_t)(lane & 15) * (AP * 2)
                          + ((lane >> 4) ? 16u : 0u);

    float o[8][4];
#pragma unroll
    for (int nt = 0; nt < 8; nt++)
        o[nt][0] = o[nt][1] = o[nt][2] = o[nt][3] = 0.f;
    float m0 = -INFINITY, m1 = -INFINITY, l0 = 0.f, l1 = 0.f;

    const int qrow0 = qb + w * 16 + lq;

    for (int kt_i = 0; kt_i < 32; kt_i++) {
        const int kb = kt_i * 64;
        const int s  = kt_i & 1;
        cp_wait0();
        __syncthreads();
        if (kt_i + 1 < 32) load_kv(kb + 64, s ^ 1);

        const uint32_t kbase = smb + (uint32_t)(ATT_K_OFF + s * KSTGH) * 2 + k_lrow;

        // ---- S = Q @ K^T : 8 n-tiles of 8 keys, ldmatrix.x4 loads 2 n-tiles
        float d[8][4];
#pragma unroll
        for (int nt = 0; nt < 8; nt++)
            d[nt][0] = d[nt][1] = d[nt][2] = d[nt][3] = 0.f;

#pragma unroll
        for (int kt = 0; kt < 4; kt++) {
#pragma unroll
            for (int ntp = 0; ntp < 4; ntp++) {
                uint32_t b0, b1, b2, b3;
                ldsm_x4(b0, b1, b2, b3,
                        kbase + (uint32_t)(ntp * 16 * AP * 2) + (uint32_t)(kt * 32));
                mma_f16(d[2*ntp],     qf[kt], b0, b1);
                mma_f16(d[2*ntp + 1], qf[kt], b2, b3);
            }
        }

        if (g_maskflag[qt * 32 + kt_i]) {
            const int* mr0 = mask + (size_t)qrow0 * Sq + kb + 2 * lr;
            const int* mr1 = mr0 + 8 * Sq;
#pragma unroll
            for (int nt = 0; nt < 8; nt++) {
                int2 a = *(const int2*)(mr0 + nt * 8);
                int2 c = *(const int2*)(mr1 + nt * 8);
                if (a.x == 0) d[nt][0] = -1e9f;
                if (a.y == 0) d[nt][1] = -1e9f;
                if (c.x == 0) d[nt][2] = -1e9f;
                if (c.y == 0) d[nt][3] = -1e9f;
            }
        }

        // ---- online softmax
        float mx0 = -INFINITY, mx1 = -INFINITY;
#pragma unroll
        for (int nt = 0; nt < 8; nt++) {
            mx0 = fmaxf(mx0, fmaxf(d[nt][0], d[nt][1]));
            mx1 = fmaxf(mx1, fmaxf(d[nt][2], d[nt][3]));
        }
        mx0 = fmaxf(mx0, __shfl_xor_sync(0xffffffffu, mx0, 1));
        mx0 = fmaxf(mx0, __shfl_xor_sync(0xffffffffu, mx0, 2));
        mx1 = fmaxf(mx1, __shfl_xor_sync(0xffffffffu, mx1, 1));
        mx1 = fmaxf(mx1, __shfl_xor_sync(0xffffffffu, mx1, 2));

        float mn0 = fmaxf(m0, mx0), mn1 = fmaxf(m1, mx1);
        float al0 = __expf(m0 - mn0), al1 = __expf(m1 - mn1);
        m0 = mn0; m1 = mn1;

        float rs0 = 0.f, rs1 = 0.f;
#pragma unroll
        for (int nt = 0; nt < 8; nt++) {
            d[nt][0] = __expf(d[nt][0] - mn0);
            d[nt][1] = __expf(d[nt][1] - mn0);
            d[nt][2] = __expf(d[nt][2] - mn1);
            d[nt][3] = __expf(d[nt][3] - mn1);
            rs0 += d[nt][0] + d[nt][1];
            rs1 += d[nt][2] + d[nt][3];
        }
        rs0 += __shfl_xor_sync(0xffffffffu, rs0, 1);
        rs0 += __shfl_xor_sync(0xffffffffu, rs0, 2);
        rs1 += __shfl_xor_sync(0xffffffffu, rs1, 1);
        rs1 += __shfl_xor_sync(0xffffffffu, rs1, 2);
        l0 = l0 * al0 + rs0;
        l1 = l1 * al1 + rs1;

#pragma unroll
        for (int nt = 0; nt < 8; nt++) {
            o[nt][0] *= al0; o[nt][1] *= al0;
            o[nt][2] *= al1; o[nt][3] *= al1;
        }

        // ---- P fragments straight from D-fragments
        uint32_t pa[4][4];
#pragma unroll
        for (int kt = 0; kt < 4; kt++) {
            pa[kt][0] = h2u(__floats2half2_rn(d[2*kt][0],   d[2*kt][1]));
            pa[kt][1] = h2u(__floats2half2_rn(d[2*kt][2],   d[2*kt][3]));
            pa[kt][2] = h2u(__floats2half2_rn(d[2*kt+1][0], d[2*kt+1][1]));
            pa[kt][3] = h2u(__floats2half2_rn(d[2*kt+1][2], d[2*kt+1][3]));
        }

        // ---- O += P @ V
        const uint32_t vbase = smb + (uint32_t)(ATT_V_OFF + s * KSTGH) * 2 + v_lrow;
#pragma unroll
        for (int ntp = 0; ntp < 4; ntp++) {
#pragma unroll
            for (int kt = 0; kt < 4; kt++) {
                uint32_t b0, b1, b2, b3;
                ldsm_x4_t(b0, b1, b2, b3,
                          vbase + (uint32_t)(kt * 16 * AP * 2) + (uint32_t)(ntp * 32));
                mma_f16(o[2*ntp],     pa[kt], b0, b1);
                mma_f16(o[2*ntp + 1], pa[kt], b2, b3);
            }
        }
    }

    // ---- epilogue
    float inv0 = 1.f / l0, inv1 = 1.f / l1;
    __half* out0 = Out + base + (size_t)qrow0 * Dm + 2 * lr;
    __half* out1 = out0 + (size_t)8 * Dm;
#pragma unroll
    for (int nt = 0; nt < 8; nt++) {
        __half2 h0 = __floats2half2_rn(o[nt][0] * inv0, o[nt][1] * inv0);
        __half2 h1 = __floats2half2_rn(o[nt][2] * inv1, o[nt][3] * inv1);
        *(uint32_t*)(out0 + nt * 8) = h2u(h0);
        *(uint32_t*)(out1 + nt * 8) = h2u(h1);
    }
}

// ===========================================================================
extern "C" void kernel_launch(void* const* d_in, const int* in_sizes, int n_in,
                              void* d_out, int out_size)
{
    (void)in_sizes; (void)n_in; (void)out_size;
    const float* query = (const float*)d_in[0];
    const float* key_  = (const float*)d_in[1];
    const float* value = (const float*)d_in[2];
    const int*   mask  = (const int*)d_in[3];
    const float* w_q   = (const float*)d_in[4];
    const float* w_k   = (const float*)d_in[5];
    const float* w_v   = (const float*)d_in[6];
    const float* w_o   = (const float*)d_in[7];
    float* out = (float*)d_out;

    __half *q, *k, *v, *attn, *xq, *xk, *xv, *wq, *wk, *wv, *wo;
    cudaGetSymbolAddress((void**)&q,    g_q);
    cudaGetSymbolAddress((void**)&k,    g_k);
    cudaGetSymbolAddress((void**)&v,    g_v);
    cudaGetSymbolAddress((void**)&attn, g_attn);
    cudaGetSymbolAddress((void**)&xq,   g_xq);
    cudaGetSymbolAddress((void**)&xk,   g_xk);
    cudaGetSymbolAddress((void**)&xv,   g_xv);
    cudaGetSymbolAddress((void**)&wq,   g_wq);
    cudaGetSymbolAddress((void**)&wk,   g_wk);
    cudaGetSymbolAddress((void**)&wv,   g_wv);
    cudaGetSymbolAddress((void**)&wo,   g_wo);

    cudaFuncSetAttribute(sgemm_qkv,
                         cudaFuncAttributeMaxDynamicSharedMemorySize, GM_SMEM_BYTES);
    cudaFuncSetAttribute(sgemm_out,
                         cudaFuncAttributeMaxDynamicSharedMemorySize, GM_SMEM_BYTES);
    cudaFuncSetAttribute(attn_mma,
                         cudaFuncAttributeMaxDynamicSharedMemorySize, ATT_SMEM_BYTES);

    const int NX4 = (Mrows * Dm) / 4;
    const int NW4 = (Dm * Dm) / 4;
    h_conv3<<<dim3(296, 1, 3), 256>>>(query, key_, value, xq, xk, xv, NX4);
    h_conv4<<<dim3(148, 1, 4), 256>>>(w_q, w_k, w_v, w_o, wq, wk, wv, wo, NW4);
    mask_flags<<<512, 256>>>(mask);

    dim3 gqkv(Dm / 128, Mrows / 128, 3);   // (8, 64, 3)
    sgemm_qkv<<<gqkv, 256, GM_SMEM_BYTES>>>(xq, xk, xv, wq, wk, wv, q, k, v);

    dim3 ga(Sq / 128, Hn, Bsz);            // (16, 16, 4)
    attn_mma<<<ga, 256, ATT_SMEM_BYTES>>>(q, k, v, mask, attn);

    dim3 gg(Dm / 128, Mrows / 128);        // (8, 64)
    sgemm_out<<<gg, 256, GM_SMEM_BYTES>>>(attn, wo, out);
}